// round 8
// baseline (speedup 1.0000x reference)
#include <cuda_runtime.h>
#include <math.h>
#include <stdint.h>

#define B_   4
#define L_   2048
#define D_   256
#define H_   4
#define NL_  4
#define V_   32000
#define DH_  64
#define FF_  (4*D_)
#define MTOK (B_*L_)

// ---------------- scratch (allocation-free: __device__ globals) ----------------
__device__ float g_x [MTOK*D_];
__device__ float g_xn[MTOK*D_];
__device__ float g_q [MTOK*D_];
__device__ float g_k [MTOK*D_];
__device__ float g_v [MTOK*D_];
__device__ float g_at[MTOK*D_];
__device__ float g_ff[MTOK*FF_];
__device__ unsigned g_a32[MTOK*D_];              // tf32, k-permuted
__device__ unsigned g_w32[(size_t)V_*D_];        // tf32, k-permuted

// ---------------- embedding ----------------
__global__ void embed_k(const int* __restrict__ ids, const int* __restrict__ tys,
                        const float* __restrict__ tok_emb, const float* __restrict__ type_emb,
                        float* __restrict__ x) {
    int i = blockIdx.x * 256 + threadIdx.x;
    int t = i / D_, d = i - t * D_;
    x[i] = tok_emb[(size_t)ids[t] * D_ + d] + type_emb[tys[t] * D_ + d];
}

// ---------------- RMSNorm ----------------
__global__ void rms_k(const float* __restrict__ x, const float* __restrict__ w,
                      float* __restrict__ y) {
    int row = blockIdx.x;
    int d = threadIdx.x;
    float v = x[(size_t)row * D_ + d];
    float s = v * v;
    __shared__ float sh[8];
    #pragma unroll
    for (int o = 16; o; o >>= 1) s += __shfl_xor_sync(0xFFFFFFFFu, s, o);
    if ((threadIdx.x & 31) == 0) sh[threadIdx.x >> 5] = s;
    __syncthreads();
    if (threadIdx.x < 8) {
        float t = sh[threadIdx.x];
        #pragma unroll
        for (int o = 4; o; o >>= 1) t += __shfl_xor_sync(0xFFu, t, o);
        if (threadIdx.x == 0) sh[0] = t;
    }
    __syncthreads();
    float mean = sh[0] * (1.0f / D_);
    float r = rsqrtf(mean + 1.1920929e-07f);
    y[(size_t)row * D_ + d] = v * r * w[d];
}

// ---------------- RoPE ----------------
__global__ void rope_k(float* __restrict__ q, float* __restrict__ k) {
    int i = blockIdx.x * 256 + threadIdx.x;
    int j  = i & 31;
    int hh = (i >> 5) & (H_ - 1);
    int t  = i >> 7;
    int pos = t & (L_ - 1);
    float freq = expf(-logf(10000.0f) * (float)j * (1.0f / 32.0f));
    float ang = (float)pos * freq;
    float c = cosf(ang), s = sinf(ang);
    size_t base = (size_t)t * D_ + hh * DH_ + j;
    float q0 = q[base], q1 = q[base + 32];
    q[base]      = q0 * c - q1 * s;
    q[base + 32] = q1 * c + q0 * s;
    float k0 = k[base], k1 = k[base + 32];
    k[base]      = k0 * c - k1 * s;
    k[base + 32] = k1 * c + k0 * s;
}

// ---------------- flash-style causal attention (lane-pair per query) ----------------
// 256 threads; threads (2i, 2i+1) share query i, each owning 32 of the 64 dims.
// Heavy (high-qt) blocks scheduled first via reversed blockIdx.x.
__global__ void __launch_bounds__(256) attn_k(const float* __restrict__ q,
                                              const float* __restrict__ k,
                                              const float* __restrict__ v,
                                              const int* __restrict__ am,
                                              float* __restrict__ out) {
    int qt = gridDim.x - 1 - blockIdx.x;
    int h = blockIdx.y, b = blockIdx.z;
    int tid = threadIdx.x;
    int ql = tid >> 1, half = tid & 1;
    int lane = tid & 31;
    unsigned pmask = 3u << (lane & 30);
    int qrow = qt * 128 + ql;
    __shared__ float Ks[64][64];
    __shared__ float Vs[64][64];
    __shared__ int   Ms[64];

    size_t qbase = ((size_t)(b * L_ + qrow)) * D_ + h * DH_ + half * 32;
    float qr[32];
    #pragma unroll
    for (int d = 0; d < 32; d++) qr[d] = q[qbase + d] * 0.125f;

    float m = -1e30f, l = 0.0f;
    float acc[32];
    #pragma unroll
    for (int d = 0; d < 32; d++) acc[d] = 0.0f;

    int ntiles = 2 * qt + 2;
    for (int kt = 0; kt < ntiles; kt++) {
        int krow0 = kt * 64;
        {   // 256 threads: each loads a 16-float quarter-row of K and V
            int r = tid >> 2, qu = (tid & 3) * 16;
            size_t gb = ((size_t)(b * L_ + krow0 + r)) * D_ + h * DH_ + qu;
            float4*       Kd = (float4*)&Ks[r][qu];
            const float4* Kg = (const float4*)(k + gb);
            float4*       Vd = (float4*)&Vs[r][qu];
            const float4* Vg = (const float4*)(v + gb);
            #pragma unroll
            for (int u = 0; u < 4; u++) { Kd[u] = Kg[u]; Vd[u] = Vg[u]; }
            if (tid < 64) Ms[tid] = am[b * L_ + krow0 + tid];
        }
        __syncthreads();
        int klim = qrow - krow0 + 1;
        if (klim > 64) klim = 64;
        for (int kk = 0; kk < klim; kk++) {
            if (Ms[kk]) {
                const float* Kr = &Ks[kk][half * 32];
                float s = 0.0f;
                #pragma unroll
                for (int d = 0; d < 32; d++) s += qr[d] * Kr[d];
                s += __shfl_xor_sync(pmask, s, 1);
                if (s > m) {
                    float c0 = expf(m - s);
                    l *= c0;
                    #pragma unroll
                    for (int d = 0; d < 32; d++) acc[d] *= c0;
                    m = s;
                }
                float p = expf(s - m);
                l += p;
                const float* Vr = &Vs[kk][half * 32];
                #pragma unroll
                for (int d = 0; d < 32; d++) acc[d] += p * Vr[d];
            }
        }
        __syncthreads();
    }
    float inv = (l > 0.0f) ? (1.0f / l) : 0.0f;
    #pragma unroll
    for (int d = 0; d < 32; d++) out[qbase + d] = acc[d] * inv;
}

// ---------------- optimized fp32 GEMM (layer path, exact) ----------------
// C[m,n] = sum_k A[m,k]*W[n,k]. 128x64x16 tile, 256 threads, 8x4 microtile,
// register-prefetch + 2-buffer smem ring (one sync per chunk).
// EPI: 0 plain, 1 residual add, 2 SiLU.
template <int EPI>
__global__ void __launch_bounds__(256) gemm_f32(const float* __restrict__ A,
                                                const float* __restrict__ W,
                                                const float* __restrict__ R,
                                                float* __restrict__ C,
                                                int M, int N, int K) {
    __shared__ __align__(16) float As[2][16][132];
    __shared__ __align__(16) float Ws[2][16][68];
    const int bm = blockIdx.y * 128, bn = blockIdx.x * 64;
    const int tid = threadIdx.x;
    const int tx = tid & 15, ty = tid >> 4;
    const int arow = tid >> 2;              // 0..63 (+64 for second half)
    const int k4 = (tid & 3) << 2;
    const float* Ap0 = A + (size_t)(bm + arow) * K + k4;
    const float* Ap1 = A + (size_t)(bm + arow + 64) * K + k4;
    const float* Wp  = W + (size_t)(bn + arow) * K + k4;

    float acc[8][4];
    #pragma unroll
    for (int i = 0; i < 8; i++)
        #pragma unroll
        for (int j = 0; j < 4; j++) acc[i][j] = 0.0f;

    float4 pa0 = *(const float4*)Ap0;
    float4 pa1 = *(const float4*)Ap1;
    float4 pw  = *(const float4*)Wp;
    {   // stage chunk 0 -> buffer 0
        float a0[4] = {pa0.x, pa0.y, pa0.z, pa0.w};
        float a1[4] = {pa1.x, pa1.y, pa1.z, pa1.w};
        float w0[4] = {pw.x,  pw.y,  pw.z,  pw.w};
        #pragma unroll
        for (int j = 0; j < 4; j++) {
            As[0][k4 + j][arow]      = a0[j];
            As[0][k4 + j][arow + 64] = a1[j];
            Ws[0][k4 + j][arow]      = w0[j];
        }
    }
    __syncthreads();

    const int nch = K >> 4;
    for (int ch = 0; ch < nch; ch++) {
        const int s = ch & 1;
        if (ch + 1 < nch) {
            pa0 = *(const float4*)(Ap0 + (ch + 1) * 16);
            pa1 = *(const float4*)(Ap1 + (ch + 1) * 16);
            pw  = *(const float4*)(Wp  + (ch + 1) * 16);
        }
        #pragma unroll
        for (int kk = 0; kk < 16; kk++) {
            float4 av0 = *(const float4*)&As[s][kk][ty * 8];
            float4 av1 = *(const float4*)&As[s][kk][ty * 8 + 4];
            float4 wv  = *(const float4*)&Ws[s][kk][tx * 4];
            float a[8] = {av0.x, av0.y, av0.z, av0.w, av1.x, av1.y, av1.z, av1.w};
            float w[4] = {wv.x, wv.y, wv.z, wv.w};
            #pragma unroll
            for (int i = 0; i < 8; i++)
                #pragma unroll
                for (int j = 0; j < 4; j++) acc[i][j] += a[i] * w[j];
        }
        if (ch + 1 < nch) {
            const int s2 = (ch + 1) & 1;
            float a0[4] = {pa0.x, pa0.y, pa0.z, pa0.w};
            float a1[4] = {pa1.x, pa1.y, pa1.z, pa1.w};
            float w0[4] = {pw.x,  pw.y,  pw.z,  pw.w};
            #pragma unroll
            for (int j = 0; j < 4; j++) {
                As[s2][k4 + j][arow]      = a0[j];
                As[s2][k4 + j][arow + 64] = a1[j];
                Ws[s2][k4 + j][arow]      = w0[j];
            }
        }
        __syncthreads();
    }

    #pragma unroll
    for (int i = 0; i < 8; i++) {
        size_t idx = (size_t)(bm + ty * 8 + i) * N + bn + tx * 4;
        float4 vv = make_float4(acc[i][0], acc[i][1], acc[i][2], acc[i][3]);
        if (EPI == 1) {
            float4 rr = *(const float4*)(R + idx);
            vv.x += rr.x; vv.y += rr.y; vv.z += rr.z; vv.w += rr.w;
        }
        if (EPI == 2) {
            vv.x = vv.x / (1.0f + expf(-vv.x));
            vv.y = vv.y / (1.0f + expf(-vv.y));
            vv.z = vv.z / (1.0f + expf(-vv.z));
            vv.w = vv.w / (1.0f + expf(-vv.w));
        }
        *(float4*)(C + idx) = vv;
    }
}

// ---------------- tf32 helpers ----------------
__device__ __forceinline__ unsigned f2tf32(float v) {
    unsigned o;
    asm("cvt.rna.tf32.f32 %0, %1;" : "=r"(o) : "f"(v));
    return o;
}
__device__ __forceinline__ int kperm(int kl) {   // kl in [0,32)
    return (kl & ~7) | ((kl & 3) << 1) | ((kl & 4) >> 2);
}
__device__ __forceinline__ int swz(int row, int col) {
    return row * 32 + (col ^ ((row & 3) << 3));
}
__device__ __forceinline__ uint32_t smem_u32(const void* p) {
    uint32_t a;
    asm("{ .reg .u64 t; cvta.to.shared.u64 t, %1; cvt.u32.u64 %0, t; }" : "=r"(a) : "l"(p));
    return a;
}
#define CP_ASYNC16(dst_u32, src_ptr) \
    asm volatile("cp.async.cg.shared.global [%0], [%1], 16;" :: "r"(dst_u32), "l"(src_ptr))
#define CP_COMMIT() asm volatile("cp.async.commit_group;" ::: "memory")
#define CP_WAIT1()  asm volatile("cp.async.wait_group 1;" ::: "memory")

// fp32 -> tf32-rounded + k-permuted (permutation stays within a 32-elem window)
__global__ void cvt_tf32_perm(const float* __restrict__ x, unsigned* __restrict__ o) {
    int i = blockIdx.x * 256 + threadIdx.x;
    int kl = i & 31;
    o[(i & ~31) | kperm(kl)] = f2tf32(x[i]);
}

// ---------------- tf32 mma.sync GEMM, cp.async double-buffered (LM head) ----------------
__global__ void __launch_bounds__(256) lm_tf32(const unsigned* __restrict__ A,
                                               const unsigned* __restrict__ W,
                                               float* __restrict__ C,
                                               int M, int N, int K) {
    extern __shared__ unsigned sbuf[];            // [2][4096] A then [2][4096] W
    unsigned* As[2] = { sbuf,        sbuf + 4096 };
    unsigned* Ws[2] = { sbuf + 8192, sbuf + 12288 };
    const uint32_t sb = smem_u32(sbuf);

    const int bm = blockIdx.y * 128, bn = blockIdx.x * 128;
    const int tid = threadIdx.x;
    const int warp = tid >> 5, lane = tid & 31;
    const int wm = warp >> 2, wn = warp & 3;
    const int gid = lane >> 2, qid = lane & 3;
    const int nchunks = K >> 5;

    auto issue = [&](int ch, int s) {
        #pragma unroll
        for (int t = 0; t < 4; t++) {
            int c2 = tid + t * 256;
            int row = c2 >> 3, col4 = (c2 & 7) << 2;
            int so = swz(row, col4);
            const unsigned* ga = A + (size_t)(bm + row) * K + ch * 32 + col4;
            const unsigned* gw = W + (size_t)(bn + row) * K + ch * 32 + col4;
            CP_ASYNC16(sb + (uint32_t)(As[s] - sbuf + so) * 4u, ga);
            CP_ASYNC16(sb + (uint32_t)(Ws[s] - sbuf + so) * 4u, gw);
        }
    };

    float cacc[4][4][4];
    #pragma unroll
    for (int i = 0; i < 4; i++)
        #pragma unroll
        for (int j = 0; j < 4; j++)
            #pragma unroll
            for (int f = 0; f < 4; f++) cacc[i][j][f] = 0.0f;

    issue(0, 0); CP_COMMIT();
    if (nchunks > 1) issue(1, 1);
    CP_COMMIT();

    for (int ch = 0; ch < nchunks; ch++) {
        const int s = ch & 1;
        CP_WAIT1();
        __syncthreads();
        const unsigned* Ab = As[s];
        const unsigned* Wb = Ws[s];
        #pragma unroll
        for (int ks = 0; ks < 4; ks++) {
            const int c0 = ks * 8 + 2 * qid;
            unsigned afr[4][4];
            unsigned bfr[4][2];
            #pragma unroll
            for (int mt = 0; mt < 4; mt++) {
                int r0 = wm * 64 + mt * 16 + gid;
                uint2 lo = *(const uint2*)&Ab[swz(r0, c0)];
                uint2 hi = *(const uint2*)&Ab[swz(r0 + 8, c0)];
                afr[mt][0] = lo.x; afr[mt][2] = lo.y;
                afr[mt][1] = hi.x; afr[mt][3] = hi.y;
            }
            #pragma unroll
            for (int nt = 0; nt < 4; nt++) {
                int rn = wn * 32 + nt * 8 + gid;
                uint2 bb = *(const uint2*)&Wb[swz(rn, c0)];
                bfr[nt][0] = bb.x; bfr[nt][1] = bb.y;
            }
            #pragma unroll
            for (int mt = 0; mt < 4; mt++)
                #pragma unroll
                for (int nt = 0; nt < 4; nt++) {
                    asm volatile(
                        "mma.sync.aligned.m16n8k8.row.col.f32.tf32.tf32.f32 "
                        "{%0,%1,%2,%3}, {%4,%5,%6,%7}, {%8,%9}, {%0,%1,%2,%3};\n"
                        : "+f"(cacc[mt][nt][0]), "+f"(cacc[mt][nt][1]),
                          "+f"(cacc[mt][nt][2]), "+f"(cacc[mt][nt][3])
                        : "r"(afr[mt][0]), "r"(afr[mt][1]),
                          "r"(afr[mt][2]), "r"(afr[mt][3]),
                          "r"(bfr[nt][0]), "r"(bfr[nt][1]));
                }
        }
        __syncthreads();
        if (ch + 2 < nchunks) issue(ch + 2, s);
        CP_COMMIT();
    }

    #pragma unroll
    for (int mt = 0; mt < 4; mt++) {
        int row = bm + wm * 64 + mt * 16 + gid;
        #pragma unroll
        for (int nt = 0; nt < 4; nt++) {
            int col = bn + wn * 32 + nt * 8 + qid * 2;
            *(float2*)(C + (size_t)row * N + col) =
                make_float2(cacc[mt][nt][0], cacc[mt][nt][1]);
            *(float2*)(C + (size_t)(row + 8) * N + col) =
                make_float2(cacc[mt][nt][2], cacc[mt][nt][3]);
        }
    }
}

// ---------------- classifier heads on cls token (b, 0) ----------------
__global__ void heads_k(const float* __restrict__ xn,
                        const float* __restrict__ rw, const float* __restrict__ rb,
                        const float* __restrict__ mw, const float* __restrict__ mb,
                        float* __restrict__ out) {
    int b = blockIdx.x;
    int t = threadIdx.x;
    float xv = xn[((size_t)b * L_) * D_ + t];
    float pr = xv * rw[t];
    float pm = xv * mw[t];
    __shared__ float sr[8], sm_[8];
    #pragma unroll
    for (int o = 16; o; o >>= 1) {
        pr += __shfl_xor_sync(0xFFFFFFFFu, pr, o);
        pm += __shfl_xor_sync(0xFFFFFFFFu, pm, o);
    }
    if ((t & 31) == 0) { sr[t >> 5] = pr; sm_[t >> 5] = pm; }
    __syncthreads();
    if (t == 0) {
        float a = 0.0f, c = 0.0f;
        #pragma unroll
        for (int i = 0; i < 8; i++) { a += sr[i]; c += sm_[i]; }
        out[b]      = a + rb[0];
        out[B_ + b] = c + mb[0];
    }
}

// ---------------- driver ----------------
extern "C" void kernel_launch(void* const* d_in, const int* in_sizes, int n_in,
                              void* d_out, int out_size) {
    const int*   token_ids    = (const int*)  d_in[0];
    const int*   token_types  = (const int*)  d_in[1];
    const int*   amask        = (const int*)  d_in[2];
    const float* tok_emb      = (const float*)d_in[3];
    const float* type_emb     = (const float*)d_in[4];
    const float* norm1_w      = (const float*)d_in[5];
    const float* wq           = (const float*)d_in[6];
    const float* wk           = (const float*)d_in[7];
    const float* wv           = (const float*)d_in[8];
    const float* wo           = (const float*)d_in[9];
    const float* norm2_w      = (const float*)d_in[10];
    const float* ff_w1        = (const float*)d_in[11];
    const float* ff_w2        = (const float*)d_in[12];
    const float* final_norm_w = (const float*)d_in[13];
    const float* lm_w         = (const float*)d_in[14];
    const float* read_w       = (const float*)d_in[15];
    const float* read_b       = (const float*)d_in[16];
    const float* mort_w       = (const float*)d_in[17];
    const float* mort_b       = (const float*)d_in[18];
    float* out = (float*)d_out;

    float *x, *xn, *q, *k, *v, *at, *ff;
    unsigned *a32, *w32;
    cudaGetSymbolAddress((void**)&x,   g_x);
    cudaGetSymbolAddress((void**)&xn,  g_xn);
    cudaGetSymbolAddress((void**)&q,   g_q);
    cudaGetSymbolAddress((void**)&k,   g_k);
    cudaGetSymbolAddress((void**)&v,   g_v);
    cudaGetSymbolAddress((void**)&at,  g_at);
    cudaGetSymbolAddress((void**)&ff,  g_ff);
    cudaGetSymbolAddress((void**)&a32, g_a32);
    cudaGetSymbolAddress((void**)&w32, g_w32);

    cudaFuncSetAttribute(lm_tf32, cudaFuncAttributeMaxDynamicSharedMemorySize, 65536);

    embed_k<<<MTOK * D_ / 256, 256>>>(token_ids, token_types, tok_emb, type_emb, x);

    dim3 gqkv(D_ / 64, MTOK / 128);
    dim3 gff1(FF_ / 64, MTOK / 128);
    for (int li = 0; li < NL_; li++) {
        rms_k<<<MTOK, 256>>>(x, norm1_w + li * D_, xn);
        gemm_f32<0><<<gqkv, 256>>>(xn, wq + (size_t)li * D_ * D_, nullptr, q, MTOK, D_, D_);
        gemm_f32<0><<<gqkv, 256>>>(xn, wk + (size_t)li * D_ * D_, nullptr, k, MTOK, D_, D_);
        gemm_f32<0><<<gqkv, 256>>>(xn, wv + (size_t)li * D_ * D_, nullptr, v, MTOK, D_, D_);
        rope_k<<<MTOK * H_ * 32 / 256, 256>>>(q, k);
        attn_k<<<dim3(L_ / 128, H_, B_), 256>>>(q, k, v, amask, at);
        gemm_f32<1><<<gqkv, 256>>>(at, wo + (size_t)li * D_ * D_, x, x, MTOK, D_, D_);
        rms_k<<<MTOK, 256>>>(x, norm2_w + li * D_, xn);
        gemm_f32<2><<<gff1, 256>>>(xn, ff_w1 + (size_t)li * FF_ * D_, nullptr, ff, MTOK, FF_, D_);
        gemm_f32<1><<<gqkv, 256>>>(ff, ff_w2 + (size_t)li * D_ * FF_, x, x, MTOK, D_, FF_);
    }
    rms_k<<<MTOK, 256>>>(x, final_norm_w, xn);
    cvt_tf32_perm<<<MTOK * D_ / 256, 256>>>(xn, a32);
    cvt_tf32_perm<<<V_ * D_ / 256, 256>>>(lm_w, w32);
    lm_tf32<<<dim3(V_ / 128, MTOK / 128), 256, 65536>>>(a32, w32, out, MTOK, V_, D_);
    heads_k<<<B_, 256>>>(xn, read_w, read_b, mort_w, mort_b, out + (size_t)MTOK * V_);
}

// round 9
// speedup vs baseline: 1.2084x; 1.2084x over previous
#include <cuda_runtime.h>
#include <math.h>
#include <stdint.h>

#define B_   4
#define L_   2048
#define D_   256
#define H_   4
#define NL_  4
#define V_   32000
#define DH_  64
#define FF_  (4*D_)
#define MTOK (B_*L_)

// ---------------- scratch (allocation-free: __device__ globals) ----------------
__device__ float g_x [MTOK*D_];
__device__ float g_xn[MTOK*D_];
__device__ float g_q [MTOK*D_];
__device__ float g_k [MTOK*D_];
__device__ float g_v [MTOK*D_];
__device__ float g_at[MTOK*D_];
__device__ float g_ff[MTOK*FF_];
__device__ unsigned g_a32[MTOK*D_];              // tf32, k-permuted
__device__ unsigned g_w32[(size_t)V_*D_];        // tf32, k-permuted

// ---------------- embedding ----------------
__global__ void embed_k(const int* __restrict__ ids, const int* __restrict__ tys,
                        const float* __restrict__ tok_emb, const float* __restrict__ type_emb,
                        float* __restrict__ x) {
    int i = blockIdx.x * 256 + threadIdx.x;
    int t = i / D_, d = i - t * D_;
    x[i] = tok_emb[(size_t)ids[t] * D_ + d] + type_emb[tys[t] * D_ + d];
}

// ---------------- RMSNorm ----------------
__global__ void rms_k(const float* __restrict__ x, const float* __restrict__ w,
                      float* __restrict__ y) {
    int row = blockIdx.x;
    int d = threadIdx.x;
    float v = x[(size_t)row * D_ + d];
    float s = v * v;
    __shared__ float sh[8];
    #pragma unroll
    for (int o = 16; o; o >>= 1) s += __shfl_xor_sync(0xFFFFFFFFu, s, o);
    if ((threadIdx.x & 31) == 0) sh[threadIdx.x >> 5] = s;
    __syncthreads();
    if (threadIdx.x < 8) {
        float t = sh[threadIdx.x];
        #pragma unroll
        for (int o = 4; o; o >>= 1) t += __shfl_xor_sync(0xFFu, t, o);
        if (threadIdx.x == 0) sh[0] = t;
    }
    __syncthreads();
    float mean = sh[0] * (1.0f / D_);
    float r = rsqrtf(mean + 1.1920929e-07f);
    y[(size_t)row * D_ + d] = v * r * w[d];
}

// ---------------- RoPE ----------------
__global__ void rope_k(float* __restrict__ q, float* __restrict__ k) {
    int i = blockIdx.x * 256 + threadIdx.x;
    int j  = i & 31;
    int hh = (i >> 5) & (H_ - 1);
    int t  = i >> 7;
    int pos = t & (L_ - 1);
    float freq = expf(-logf(10000.0f) * (float)j * (1.0f / 32.0f));
    float ang = (float)pos * freq;
    float c = cosf(ang), s = sinf(ang);
    size_t base = (size_t)t * D_ + hh * DH_ + j;
    float q0 = q[base], q1 = q[base + 32];
    q[base]      = q0 * c - q1 * s;
    q[base + 32] = q1 * c + q0 * s;
    float k0 = k[base], k1 = k[base + 32];
    k[base]      = k0 * c - k1 * s;
    k[base + 32] = k1 * c + k0 * s;
}

// ---------------- flash-style causal attention (R6-proven form) ----------------
// 128 threads, one query per thread, full 64-dim in registers; no shfl in the
// key loop. Heavy (high-qt) blocks scheduled first via reversed blockIdx.x.
__global__ void __launch_bounds__(128) attn_k(const float* __restrict__ q,
                                              const float* __restrict__ k,
                                              const float* __restrict__ v,
                                              const int* __restrict__ am,
                                              float* __restrict__ out) {
    int qt = gridDim.x - 1 - blockIdx.x;
    int h = blockIdx.y, b = blockIdx.z;
    int qrow = qt * 128 + threadIdx.x;
    __shared__ float Ks[64][64];
    __shared__ float Vs[64][64];
    __shared__ int   Ms[64];

    float qr[64];
    size_t qbase = ((size_t)(b * L_ + qrow)) * D_ + h * DH_;
    #pragma unroll
    for (int d = 0; d < 64; d++) qr[d] = q[qbase + d] * 0.125f;

    float m = -1e30f, l = 0.0f;
    float acc[64];
    #pragma unroll
    for (int d = 0; d < 64; d++) acc[d] = 0.0f;

    int ntiles = 2 * qt + 2;
    for (int kt = 0; kt < ntiles; kt++) {
        int krow0 = kt * 64;
        {
            int r = threadIdx.x >> 1, half = (threadIdx.x & 1) * 32;
            size_t gb = ((size_t)(b * L_ + krow0 + r)) * D_ + h * DH_ + half;
            float4*       Kd = (float4*)&Ks[r][half];
            const float4* Kg = (const float4*)(k + gb);
            float4*       Vd = (float4*)&Vs[r][half];
            const float4* Vg = (const float4*)(v + gb);
            #pragma unroll
            for (int u = 0; u < 8; u++) { Kd[u] = Kg[u]; Vd[u] = Vg[u]; }
            if (threadIdx.x < 64) Ms[threadIdx.x] = am[b * L_ + krow0 + threadIdx.x];
        }
        __syncthreads();
        int klim = qrow - krow0 + 1;
        if (klim > 64) klim = 64;
        for (int kk = 0; kk < klim; kk++) {
            if (Ms[kk]) {
                float s = 0.0f;
                #pragma unroll
                for (int d = 0; d < 64; d++) s += qr[d] * Ks[kk][d];
                if (s > m) {
                    float c0 = expf(m - s);
                    l *= c0;
                    #pragma unroll
                    for (int d = 0; d < 64; d++) acc[d] *= c0;
                    m = s;
                }
                float p = expf(s - m);
                l += p;
                #pragma unroll
                for (int d = 0; d < 64; d++) acc[d] += p * Vs[kk][d];
            }
        }
        __syncthreads();
    }
    float inv = (l > 0.0f) ? (1.0f / l) : 0.0f;
    #pragma unroll
    for (int d = 0; d < 64; d++) out[qbase + d] = acc[d] * inv;
}

// ---------------- optimized fp32 GEMM (layer path, exact; R8-proven) ----------------
// C[m,n] = sum_k A[m,k]*W[n,k]. 128x64x16 tile, 256 threads, 8x4 microtile,
// register-prefetch + 2-buffer smem ring (one sync per chunk).
// EPI: 0 plain, 1 residual add, 2 SiLU.
template <int EPI>
__global__ void __launch_bounds__(256) gemm_f32(const float* __restrict__ A,
                                                const float* __restrict__ W,
                                                const float* __restrict__ R,
                                                float* __restrict__ C,
                                                int M, int N, int K) {
    __shared__ __align__(16) float As[2][16][132];
    __shared__ __align__(16) float Ws[2][16][68];
    const int bm = blockIdx.y * 128, bn = blockIdx.x * 64;
    const int tid = threadIdx.x;
    const int tx = tid & 15, ty = tid >> 4;
    const int arow = tid >> 2;              // 0..63 (+64 for second half)
    const int k4 = (tid & 3) << 2;
    const float* Ap0 = A + (size_t)(bm + arow) * K + k4;
    const float* Ap1 = A + (size_t)(bm + arow + 64) * K + k4;
    const float* Wp  = W + (size_t)(bn + arow) * K + k4;

    float acc[8][4];
    #pragma unroll
    for (int i = 0; i < 8; i++)
        #pragma unroll
        for (int j = 0; j < 4; j++) acc[i][j] = 0.0f;

    float4 pa0 = *(const float4*)Ap0;
    float4 pa1 = *(const float4*)Ap1;
    float4 pw  = *(const float4*)Wp;
    {   // stage chunk 0 -> buffer 0
        float a0[4] = {pa0.x, pa0.y, pa0.z, pa0.w};
        float a1[4] = {pa1.x, pa1.y, pa1.z, pa1.w};
        float w0[4] = {pw.x,  pw.y,  pw.z,  pw.w};
        #pragma unroll
        for (int j = 0; j < 4; j++) {
            As[0][k4 + j][arow]      = a0[j];
            As[0][k4 + j][arow + 64] = a1[j];
            Ws[0][k4 + j][arow]      = w0[j];
        }
    }
    __syncthreads();

    const int nch = K >> 4;
    for (int ch = 0; ch < nch; ch++) {
        const int s = ch & 1;
        if (ch + 1 < nch) {
            pa0 = *(const float4*)(Ap0 + (ch + 1) * 16);
            pa1 = *(const float4*)(Ap1 + (ch + 1) * 16);
            pw  = *(const float4*)(Wp  + (ch + 1) * 16);
        }
        #pragma unroll
        for (int kk = 0; kk < 16; kk++) {
            float4 av0 = *(const float4*)&As[s][kk][ty * 8];
            float4 av1 = *(const float4*)&As[s][kk][ty * 8 + 4];
            float4 wv  = *(const float4*)&Ws[s][kk][tx * 4];
            float a[8] = {av0.x, av0.y, av0.z, av0.w, av1.x, av1.y, av1.z, av1.w};
            float w[4] = {wv.x, wv.y, wv.z, wv.w};
            #pragma unroll
            for (int i = 0; i < 8; i++)
                #pragma unroll
                for (int j = 0; j < 4; j++) acc[i][j] += a[i] * w[j];
        }
        if (ch + 1 < nch) {
            const int s2 = (ch + 1) & 1;
            float a0[4] = {pa0.x, pa0.y, pa0.z, pa0.w};
            float a1[4] = {pa1.x, pa1.y, pa1.z, pa1.w};
            float w0[4] = {pw.x,  pw.y,  pw.z,  pw.w};
            #pragma unroll
            for (int j = 0; j < 4; j++) {
                As[s2][k4 + j][arow]      = a0[j];
                As[s2][k4 + j][arow + 64] = a1[j];
                Ws[s2][k4 + j][arow]      = w0[j];
            }
        }
        __syncthreads();
    }

    #pragma unroll
    for (int i = 0; i < 8; i++) {
        size_t idx = (size_t)(bm + ty * 8 + i) * N + bn + tx * 4;
        float4 vv = make_float4(acc[i][0], acc[i][1], acc[i][2], acc[i][3]);
        if (EPI == 1) {
            float4 rr = *(const float4*)(R + idx);
            vv.x += rr.x; vv.y += rr.y; vv.z += rr.z; vv.w += rr.w;
        }
        if (EPI == 2) {
            vv.x = vv.x / (1.0f + expf(-vv.x));
            vv.y = vv.y / (1.0f + expf(-vv.y));
            vv.z = vv.z / (1.0f + expf(-vv.z));
            vv.w = vv.w / (1.0f + expf(-vv.w));
        }
        *(float4*)(C + idx) = vv;
    }
}

// ---------------- tf32 helpers ----------------
__device__ __forceinline__ unsigned f2tf32(float v) {
    unsigned o;
    asm("cvt.rna.tf32.f32 %0, %1;" : "=r"(o) : "f"(v));
    return o;
}
__device__ __forceinline__ int kperm(int kl) {   // kl in [0,32)
    return (kl & ~7) | ((kl & 3) << 1) | ((kl & 4) >> 2);
}
__device__ __forceinline__ int swz(int row, int col) {
    return row * 32 + (col ^ ((row & 3) << 3));
}
__device__ __forceinline__ uint32_t smem_u32(const void* p) {
    uint32_t a;
    asm("{ .reg .u64 t; cvta.to.shared.u64 t, %1; cvt.u32.u64 %0, t; }" : "=r"(a) : "l"(p));
    return a;
}
#define CP_ASYNC16(dst_u32, src_ptr) \
    asm volatile("cp.async.cg.shared.global [%0], [%1], 16;" :: "r"(dst_u32), "l"(src_ptr))
#define CP_COMMIT() asm volatile("cp.async.commit_group;" ::: "memory")
#define CP_WAIT1()  asm volatile("cp.async.wait_group 1;" ::: "memory")

// fp32 -> tf32-rounded + k-permuted (permutation stays within a 32-elem window)
__global__ void cvt_tf32_perm(const float* __restrict__ x, unsigned* __restrict__ o) {
    int i = blockIdx.x * 256 + threadIdx.x;
    int kl = i & 31;
    o[(i & ~31) | kperm(kl)] = f2tf32(x[i]);
}

// ---------------- tf32 mma.sync GEMM, cp.async double-buffered (LM head) ----------------
__global__ void __launch_bounds__(256) lm_tf32(const unsigned* __restrict__ A,
                                               const unsigned* __restrict__ W,
                                               float* __restrict__ C,
                                               int M, int N, int K) {
    extern __shared__ unsigned sbuf[];            // [2][4096] A then [2][4096] W
    unsigned* As[2] = { sbuf,        sbuf + 4096 };
    unsigned* Ws[2] = { sbuf + 8192, sbuf + 12288 };
    const uint32_t sb = smem_u32(sbuf);

    const int bm = blockIdx.y * 128, bn = blockIdx.x * 128;
    const int tid = threadIdx.x;
    const int warp = tid >> 5, lane = tid & 31;
    const int wm = warp >> 2, wn = warp & 3;
    const int gid = lane >> 2, qid = lane & 3;
    const int nchunks = K >> 5;

    auto issue = [&](int ch, int s) {
        #pragma unroll
        for (int t = 0; t < 4; t++) {
            int c2 = tid + t * 256;
            int row = c2 >> 3, col4 = (c2 & 7) << 2;
            int so = swz(row, col4);
            const unsigned* ga = A + (size_t)(bm + row) * K + ch * 32 + col4;
            const unsigned* gw = W + (size_t)(bn + row) * K + ch * 32 + col4;
            CP_ASYNC16(sb + (uint32_t)(As[s] - sbuf + so) * 4u, ga);
            CP_ASYNC16(sb + (uint32_t)(Ws[s] - sbuf + so) * 4u, gw);
        }
    };

    float cacc[4][4][4];
    #pragma unroll
    for (int i = 0; i < 4; i++)
        #pragma unroll
        for (int j = 0; j < 4; j++)
            #pragma unroll
            for (int f = 0; f < 4; f++) cacc[i][j][f] = 0.0f;

    issue(0, 0); CP_COMMIT();
    if (nchunks > 1) issue(1, 1);
    CP_COMMIT();

    for (int ch = 0; ch < nchunks; ch++) {
        const int s = ch & 1;
        CP_WAIT1();
        __syncthreads();
        const unsigned* Ab = As[s];
        const unsigned* Wb = Ws[s];
        #pragma unroll
        for (int ks = 0; ks < 4; ks++) {
            const int c0 = ks * 8 + 2 * qid;
            unsigned afr[4][4];
            unsigned bfr[4][2];
            #pragma unroll
            for (int mt = 0; mt < 4; mt++) {
                int r0 = wm * 64 + mt * 16 + gid;
                uint2 lo = *(const uint2*)&Ab[swz(r0, c0)];
                uint2 hi = *(const uint2*)&Ab[swz(r0 + 8, c0)];
                afr[mt][0] = lo.x; afr[mt][2] = lo.y;
                afr[mt][1] = hi.x; afr[mt][3] = hi.y;
            }
            #pragma unroll
            for (int nt = 0; nt < 4; nt++) {
                int rn = wn * 32 + nt * 8 + gid;
                uint2 bb = *(const uint2*)&Wb[swz(rn, c0)];
                bfr[nt][0] = bb.x; bfr[nt][1] = bb.y;
            }
            #pragma unroll
            for (int mt = 0; mt < 4; mt++)
                #pragma unroll
                for (int nt = 0; nt < 4; nt++) {
                    asm volatile(
                        "mma.sync.aligned.m16n8k8.row.col.f32.tf32.tf32.f32 "
                        "{%0,%1,%2,%3}, {%4,%5,%6,%7}, {%8,%9}, {%0,%1,%2,%3};\n"
                        : "+f"(cacc[mt][nt][0]), "+f"(cacc[mt][nt][1]),
                          "+f"(cacc[mt][nt][2]), "+f"(cacc[mt][nt][3])
                        : "r"(afr[mt][0]), "r"(afr[mt][1]),
                          "r"(afr[mt][2]), "r"(afr[mt][3]),
                          "r"(bfr[nt][0]), "r"(bfr[nt][1]));
                }
        }
        __syncthreads();
        if (ch + 2 < nchunks) issue(ch + 2, s);
        CP_COMMIT();
    }

    #pragma unroll
    for (int mt = 0; mt < 4; mt++) {
        int row = bm + wm * 64 + mt * 16 + gid;
        #pragma unroll
        for (int nt = 0; nt < 4; nt++) {
            int col = bn + wn * 32 + nt * 8 + qid * 2;
            *(float2*)(C + (size_t)row * N + col) =
                make_float2(cacc[mt][nt][0], cacc[mt][nt][1]);
            *(float2*)(C + (size_t)(row + 8) * N + col) =
                make_float2(cacc[mt][nt][2], cacc[mt][nt][3]);
        }
    }
}

// ---------------- classifier heads on cls token (b, 0) ----------------
__global__ void heads_k(const float* __restrict__ xn,
                        const float* __restrict__ rw, const float* __restrict__ rb,
                        const float* __restrict__ mw, const float* __restrict__ mb,
                        float* __restrict__ out) {
    int b = blockIdx.x;
    int t = threadIdx.x;
    float xv = xn[((size_t)b * L_) * D_ + t];
    float pr = xv * rw[t];
    float pm = xv * mw[t];
    __shared__ float sr[8], sm_[8];
    #pragma unroll
    for (int o = 16; o; o >>= 1) {
        pr += __shfl_xor_sync(0xFFFFFFFFu, pr, o);
        pm += __shfl_xor_sync(0xFFFFFFFFu, pm, o);
    }
    if ((t & 31) == 0) { sr[t >> 5] = pr; sm_[t >> 5] = pm; }
    __syncthreads();
    if (t == 0) {
        float a = 0.0f, c = 0.0f;
        #pragma unroll
        for (int i = 0; i < 8; i++) { a += sr[i]; c += sm_[i]; }
        out[b]      = a + rb[0];
        out[B_ + b] = c + mb[0];
    }
}

// ---------------- driver ----------------
extern "C" void kernel_launch(void* const* d_in, const int* in_sizes, int n_in,
                              void* d_out, int out_size) {
    const int*   token_ids    = (const int*)  d_in[0];
    const int*   token_types  = (const int*)  d_in[1];
    const int*   amask        = (const int*)  d_in[2];
    const float* tok_emb      = (const float*)d_in[3];
    const float* type_emb     = (const float*)d_in[4];
    const float* norm1_w      = (const float*)d_in[5];
    const float* wq           = (const float*)d_in[6];
    const float* wk           = (const float*)d_in[7];
    const float* wv           = (const float*)d_in[8];
    const float* wo           = (const float*)d_in[9];
    const float* norm2_w      = (const float*)d_in[10];
    const float* ff_w1        = (const float*)d_in[11];
    const float* ff_w2        = (const float*)d_in[12];
    const float* final_norm_w = (const float*)d_in[13];
    const float* lm_w         = (const float*)d_in[14];
    const float* read_w       = (const float*)d_in[15];
    const float* read_b       = (const float*)d_in[16];
    const float* mort_w       = (const float*)d_in[17];
    const float* mort_b       = (const float*)d_in[18];
    float* out = (float*)d_out;

    float *x, *xn, *q, *k, *v, *at, *ff;
    unsigned *a32, *w32;
    cudaGetSymbolAddress((void**)&x,   g_x);
    cudaGetSymbolAddress((void**)&xn,  g_xn);
    cudaGetSymbolAddress((void**)&q,   g_q);
    cudaGetSymbolAddress((void**)&k,   g_k);
    cudaGetSymbolAddress((void**)&v,   g_v);
    cudaGetSymbolAddress((void**)&at,  g_at);
    cudaGetSymbolAddress((void**)&ff,  g_ff);
    cudaGetSymbolAddress((void**)&a32, g_a32);
    cudaGetSymbolAddress((void**)&w32, g_w32);

    cudaFuncSetAttribute(lm_tf32, cudaFuncAttributeMaxDynamicSharedMemorySize, 65536);

    embed_k<<<MTOK * D_ / 256, 256>>>(token_ids, token_types, tok_emb, type_emb, x);

    dim3 gqkv(D_ / 64, MTOK / 128);
    dim3 gff1(FF_ / 64, MTOK / 128);
    for (int li = 0; li < NL_; li++) {
        rms_k<<<MTOK, 256>>>(x, norm1_w + li * D_, xn);
        gemm_f32<0><<<gqkv, 256>>>(xn, wq + (size_t)li * D_ * D_, nullptr, q, MTOK, D_, D_);
        gemm_f32<0><<<gqkv, 256>>>(xn, wk + (size_t)li * D_ * D_, nullptr, k, MTOK, D_, D_);
        gemm_f32<0><<<gqkv, 256>>>(xn, wv + (size_t)li * D_ * D_, nullptr, v, MTOK, D_, D_);
        rope_k<<<MTOK * H_ * 32 / 256, 256>>>(q, k);
        attn_k<<<dim3(L_ / 128, H_, B_), 128>>>(q, k, v, amask, at);
        gemm_f32<1><<<gqkv, 256>>>(at, wo + (size_t)li * D_ * D_, x, x, MTOK, D_, D_);
        rms_k<<<MTOK, 256>>>(x, norm2_w + li * D_, xn);
        gemm_f32<2><<<gff1, 256>>>(xn, ff_w1 + (size_t)li * FF_ * D_, nullptr, ff, MTOK, FF_, D_);
        gemm_f32<1><<<gqkv, 256>>>(ff, ff_w2 + (size_t)li * D_ * FF_, x, x, MTOK, D_, FF_);
    }
    rms_k<<<MTOK, 256>>>(x, final_norm_w, xn);
    cvt_tf32_perm<<<MTOK * D_ / 256, 256>>>(xn, a32);
    cvt_tf32_perm<<<V_ * D_ / 256, 256>>>(lm_w, w32);
    lm_tf32<<<dim3(V_ / 128, MTOK / 128), 256, 65536>>>(a32, w32, out, MTOK, V_, D_);
    heads_k<<<B_, 256>>>(xn, read_w, read_b, mort_w, mort_b, out + (size_t)MTOK * V_);
}

// round 10
// speedup vs baseline: 1.2717x; 1.0524x over previous
#include <cuda_runtime.h>
#include <math.h>
#include <stdint.h>

#define B_   4
#define L_   2048
#define D_   256
#define H_   4
#define NL_  4
#define V_   32000
#define DH_  64
#define FF_  (4*D_)
#define MTOK (B_*L_)

// ---------------- scratch (allocation-free: __device__ globals) ----------------
__device__ float g_x [MTOK*D_];
__device__ float g_xn[MTOK*D_];
__device__ float g_q [MTOK*D_];
__device__ float g_k [MTOK*D_];
__device__ float g_v [MTOK*D_];
__device__ float g_at[MTOK*D_];
__device__ float g_ff[MTOK*FF_];
__device__ unsigned g_a32[MTOK*D_];              // tf32, k-permuted
__device__ unsigned g_w32[(size_t)V_*D_];        // tf32, k-permuted

// ---------------- embedding ----------------
__global__ void embed_k(const int* __restrict__ ids, const int* __restrict__ tys,
                        const float* __restrict__ tok_emb, const float* __restrict__ type_emb,
                        float* __restrict__ x) {
    int i = blockIdx.x * 256 + threadIdx.x;
    int t = i / D_, d = i - t * D_;
    x[i] = tok_emb[(size_t)ids[t] * D_ + d] + type_emb[tys[t] * D_ + d];
}

// ---------------- RMSNorm ----------------
__global__ void rms_k(const float* __restrict__ x, const float* __restrict__ w,
                      float* __restrict__ y) {
    int row = blockIdx.x;
    int d = threadIdx.x;
    float v = x[(size_t)row * D_ + d];
    float s = v * v;
    __shared__ float sh[8];
    #pragma unroll
    for (int o = 16; o; o >>= 1) s += __shfl_xor_sync(0xFFFFFFFFu, s, o);
    if ((threadIdx.x & 31) == 0) sh[threadIdx.x >> 5] = s;
    __syncthreads();
    if (threadIdx.x < 8) {
        float t = sh[threadIdx.x];
        #pragma unroll
        for (int o = 4; o; o >>= 1) t += __shfl_xor_sync(0xFFu, t, o);
        if (threadIdx.x == 0) sh[0] = t;
    }
    __syncthreads();
    float mean = sh[0] * (1.0f / D_);
    float r = rsqrtf(mean + 1.1920929e-07f);
    y[(size_t)row * D_ + d] = v * r * w[d];
}

// ---------------- RoPE ----------------
__global__ void rope_k(float* __restrict__ q, float* __restrict__ k) {
    int i = blockIdx.x * 256 + threadIdx.x;
    int j  = i & 31;
    int hh = (i >> 5) & (H_ - 1);
    int t  = i >> 7;
    int pos = t & (L_ - 1);
    float freq = expf(-logf(10000.0f) * (float)j * (1.0f / 32.0f));
    float ang = (float)pos * freq;
    float c = cosf(ang), s = sinf(ang);
    size_t base = (size_t)t * D_ + hh * DH_ + j;
    float q0 = q[base], q1 = q[base + 32];
    q[base]      = q0 * c - q1 * s;
    q[base + 32] = q1 * c + q0 * s;
    float k0 = k[base], k1 = k[base + 32];
    k[base]      = k0 * c - k1 * s;
    k[base + 32] = k1 * c + k0 * s;
}

// ---------------- flash-style causal attention ----------------
// 128 threads, one query per thread, full 64-dim in registers.
// 4-way partial sums break the serial dot chain; __expf for softmax exps.
__global__ void __launch_bounds__(128) attn_k(const float* __restrict__ q,
                                              const float* __restrict__ k,
                                              const float* __restrict__ v,
                                              const int* __restrict__ am,
                                              float* __restrict__ out) {
    int qt = gridDim.x - 1 - blockIdx.x;
    int h = blockIdx.y, b = blockIdx.z;
    int qrow = qt * 128 + threadIdx.x;
    __shared__ float Ks[64][64];
    __shared__ float Vs[64][64];
    __shared__ int   Ms[64];

    float qr[64];
    size_t qbase = ((size_t)(b * L_ + qrow)) * D_ + h * DH_;
    #pragma unroll
    for (int d = 0; d < 64; d++) qr[d] = q[qbase + d] * 0.125f;

    float m = -1e30f, l = 0.0f;
    float acc[64];
    #pragma unroll
    for (int d = 0; d < 64; d++) acc[d] = 0.0f;

    int ntiles = 2 * qt + 2;
    for (int kt = 0; kt < ntiles; kt++) {
        int krow0 = kt * 64;
        {
            int r = threadIdx.x >> 1, half = (threadIdx.x & 1) * 32;
            size_t gb = ((size_t)(b * L_ + krow0 + r)) * D_ + h * DH_ + half;
            float4*       Kd = (float4*)&Ks[r][half];
            const float4* Kg = (const float4*)(k + gb);
            float4*       Vd = (float4*)&Vs[r][half];
            const float4* Vg = (const float4*)(v + gb);
            #pragma unroll
            for (int u = 0; u < 8; u++) { Kd[u] = Kg[u]; Vd[u] = Vg[u]; }
            if (threadIdx.x < 64) Ms[threadIdx.x] = am[b * L_ + krow0 + threadIdx.x];
        }
        __syncthreads();
        int klim = qrow - krow0 + 1;
        if (klim > 64) klim = 64;
        for (int kk = 0; kk < klim; kk++) {
            if (Ms[kk]) {
                float s0 = 0.0f, s1 = 0.0f, s2 = 0.0f, s3 = 0.0f;
                #pragma unroll
                for (int d = 0; d < 64; d += 4) {
                    s0 += qr[d]     * Ks[kk][d];
                    s1 += qr[d + 1] * Ks[kk][d + 1];
                    s2 += qr[d + 2] * Ks[kk][d + 2];
                    s3 += qr[d + 3] * Ks[kk][d + 3];
                }
                float s = (s0 + s1) + (s2 + s3);
                if (s > m) {
                    float c0 = __expf(m - s);
                    l *= c0;
                    #pragma unroll
                    for (int d = 0; d < 64; d++) acc[d] *= c0;
                    m = s;
                }
                float p = __expf(s - m);
                l += p;
                #pragma unroll
                for (int d = 0; d < 64; d++) acc[d] += p * Vs[kk][d];
            }
        }
        __syncthreads();
    }
    float inv = (l > 0.0f) ? (1.0f / l) : 0.0f;
    #pragma unroll
    for (int d = 0; d < 64; d++) out[qbase + d] = acc[d] * inv;
}

// ---------------- fp32 GEMM body (layer path, exact; R8-proven) ----------------
// C[m,n] = sum_k A[m,k]*W[n,k]. 128x64x16 tile, 256 threads, 8x4 microtile,
// register-prefetch + 2-buffer smem ring. EPI: 0 plain, 1 residual, 2 SiLU.
template <int EPI>
__device__ __forceinline__ void gemm_body(const float* __restrict__ A,
                                          const float* __restrict__ W,
                                          const float* __restrict__ R,
                                          float* __restrict__ C,
                                          int N, int K, int bm, int bn) {
    __shared__ __align__(16) float As[2][16][132];
    __shared__ __align__(16) float Ws[2][16][68];
    const int tid = threadIdx.x;
    const int tx = tid & 15, ty = tid >> 4;
    const int arow = tid >> 2;
    const int k4 = (tid & 3) << 2;
    const float* Ap0 = A + (size_t)(bm + arow) * K + k4;
    const float* Ap1 = A + (size_t)(bm + arow + 64) * K + k4;
    const float* Wp  = W + (size_t)(bn + arow) * K + k4;

    float acc[8][4];
    #pragma unroll
    for (int i = 0; i < 8; i++)
        #pragma unroll
        for (int j = 0; j < 4; j++) acc[i][j] = 0.0f;

    float4 pa0 = *(const float4*)Ap0;
    float4 pa1 = *(const float4*)Ap1;
    float4 pw  = *(const float4*)Wp;
    {
        float a0[4] = {pa0.x, pa0.y, pa0.z, pa0.w};
        float a1[4] = {pa1.x, pa1.y, pa1.z, pa1.w};
        float w0[4] = {pw.x,  pw.y,  pw.z,  pw.w};
        #pragma unroll
        for (int j = 0; j < 4; j++) {
            As[0][k4 + j][arow]      = a0[j];
            As[0][k4 + j][arow + 64] = a1[j];
            Ws[0][k4 + j][arow]      = w0[j];
        }
    }
    __syncthreads();

    const int nch = K >> 4;
    for (int ch = 0; ch < nch; ch++) {
        const int s = ch & 1;
        if (ch + 1 < nch) {
            pa0 = *(const float4*)(Ap0 + (ch + 1) * 16);
            pa1 = *(const float4*)(Ap1 + (ch + 1) * 16);
            pw  = *(const float4*)(Wp  + (ch + 1) * 16);
        }
        #pragma unroll
        for (int kk = 0; kk < 16; kk++) {
            float4 av0 = *(const float4*)&As[s][kk][ty * 8];
            float4 av1 = *(const float4*)&As[s][kk][ty * 8 + 4];
            float4 wv  = *(const float4*)&Ws[s][kk][tx * 4];
            float a[8] = {av0.x, av0.y, av0.z, av0.w, av1.x, av1.y, av1.z, av1.w};
            float w[4] = {wv.x, wv.y, wv.z, wv.w};
            #pragma unroll
            for (int i = 0; i < 8; i++)
                #pragma unroll
                for (int j = 0; j < 4; j++) acc[i][j] += a[i] * w[j];
        }
        if (ch + 1 < nch) {
            const int s2 = (ch + 1) & 1;
            float a0[4] = {pa0.x, pa0.y, pa0.z, pa0.w};
            float a1[4] = {pa1.x, pa1.y, pa1.z, pa1.w};
            float w0[4] = {pw.x,  pw.y,  pw.z,  pw.w};
            #pragma unroll
            for (int j = 0; j < 4; j++) {
                As[s2][k4 + j][arow]      = a0[j];
                As[s2][k4 + j][arow + 64] = a1[j];
                Ws[s2][k4 + j][arow]      = w0[j];
            }
        }
        __syncthreads();
    }

    #pragma unroll
    for (int i = 0; i < 8; i++) {
        size_t idx = (size_t)(bm + ty * 8 + i) * N + bn + tx * 4;
        float4 vv = make_float4(acc[i][0], acc[i][1], acc[i][2], acc[i][3]);
        if (EPI == 1) {
            float4 rr = *(const float4*)(R + idx);
            vv.x += rr.x; vv.y += rr.y; vv.z += rr.z; vv.w += rr.w;
        }
        if (EPI == 2) {
            vv.x = vv.x / (1.0f + expf(-vv.x));
            vv.y = vv.y / (1.0f + expf(-vv.y));
            vv.z = vv.z / (1.0f + expf(-vv.z));
            vv.w = vv.w / (1.0f + expf(-vv.w));
        }
        *(float4*)(C + idx) = vv;
    }
}

template <int EPI>
__global__ void __launch_bounds__(256) gemm_f32(const float* __restrict__ A,
                                                const float* __restrict__ W,
                                                const float* __restrict__ R,
                                                float* __restrict__ C,
                                                int M, int N, int K) {
    gemm_body<EPI>(A, W, R, C, N, K, blockIdx.y * 128, blockIdx.x * 64);
}

// fused Q/K/V projection: one launch, blockIdx.x selects matrix + n-tile
__global__ void __launch_bounds__(256) gemm_qkv(const float* __restrict__ A,
                                                const float* __restrict__ Wq,
                                                const float* __restrict__ Wk,
                                                const float* __restrict__ Wv,
                                                float* __restrict__ q,
                                                float* __restrict__ kk,
                                                float* __restrict__ vv,
                                                int K) {
    int sel = blockIdx.x >> 2;
    const float* W = (sel == 0) ? Wq : (sel == 1) ? Wk : Wv;
    float*       C = (sel == 0) ? q  : (sel == 1) ? kk : vv;
    gemm_body<0>(A, W, nullptr, C, D_, K, blockIdx.y * 128, (blockIdx.x & 3) * 64);
}

// ---------------- tf32 helpers ----------------
__device__ __forceinline__ unsigned f2tf32(float v) {
    unsigned o;
    asm("cvt.rna.tf32.f32 %0, %1;" : "=r"(o) : "f"(v));
    return o;
}
__device__ __forceinline__ int kperm(int kl) {   // kl in [0,32)
    return (kl & ~7) | ((kl & 3) << 1) | ((kl & 4) >> 2);
}
__device__ __forceinline__ int swz(int row, int col) {
    return row * 32 + (col ^ ((row & 3) << 3));
}
__device__ __forceinline__ uint32_t smem_u32(const void* p) {
    uint32_t a;
    asm("{ .reg .u64 t; cvta.to.shared.u64 t, %1; cvt.u32.u64 %0, t; }" : "=r"(a) : "l"(p));
    return a;
}
#define CP_ASYNC16(dst_u32, src_ptr) \
    asm volatile("cp.async.cg.shared.global [%0], [%1], 16;" :: "r"(dst_u32), "l"(src_ptr))
#define CP_COMMIT() asm volatile("cp.async.commit_group;" ::: "memory")
#define CP_WAIT1()  asm volatile("cp.async.wait_group 1;" ::: "memory")

// fp32 -> tf32-rounded + k-permuted (permutation stays within a 32-elem window)
__global__ void cvt_tf32_perm(const float* __restrict__ x, unsigned* __restrict__ o) {
    int i = blockIdx.x * 256 + threadIdx.x;
    int kl = i & 31;
    o[(i & ~31) | kperm(kl)] = f2tf32(x[i]);
}

// ---------------- tf32 mma.sync GEMM, cp.async double-buffered (LM head) ----------------
// __launch_bounds__(256, 2): cap regs at 128 to get 2 CTAs/SM (latency hiding).
__global__ void __launch_bounds__(256, 2) lm_tf32(const unsigned* __restrict__ A,
                                                  const unsigned* __restrict__ W,
                                                  float* __restrict__ C,
                                                  int M, int N, int K) {
    extern __shared__ unsigned sbuf[];            // [2][4096] A then [2][4096] W
    unsigned* As[2] = { sbuf,        sbuf + 4096 };
    unsigned* Ws[2] = { sbuf + 8192, sbuf + 12288 };
    const uint32_t sb = smem_u32(sbuf);

    const int bm = blockIdx.y * 128, bn = blockIdx.x * 128;
    const int tid = threadIdx.x;
    const int warp = tid >> 5, lane = tid & 31;
    const int wm = warp >> 2, wn = warp & 3;
    const int gid = lane >> 2, qid = lane & 3;
    const int nchunks = K >> 5;

    auto issue = [&](int ch, int s) {
        #pragma unroll
        for (int t = 0; t < 4; t++) {
            int c2 = tid + t * 256;
            int row = c2 >> 3, col4 = (c2 & 7) << 2;
            int so = swz(row, col4);
            const unsigned* ga = A + (size_t)(bm + row) * K + ch * 32 + col4;
            const unsigned* gw = W + (size_t)(bn + row) * K + ch * 32 + col4;
            CP_ASYNC16(sb + (uint32_t)(As[s] - sbuf + so) * 4u, ga);
            CP_ASYNC16(sb + (uint32_t)(Ws[s] - sbuf + so) * 4u, gw);
        }
    };

    float cacc[4][4][4];
    #pragma unroll
    for (int i = 0; i < 4; i++)
        #pragma unroll
        for (int j = 0; j < 4; j++)
            #pragma unroll
            for (int f = 0; f < 4; f++) cacc[i][j][f] = 0.0f;

    issue(0, 0); CP_COMMIT();
    if (nchunks > 1) issue(1, 1);
    CP_COMMIT();

    for (int ch = 0; ch < nchunks; ch++) {
        const int s = ch & 1;
        CP_WAIT1();
        __syncthreads();
        const unsigned* Ab = As[s];
        const unsigned* Wb = Ws[s];
        #pragma unroll
        for (int ks = 0; ks < 4; ks++) {
            const int c0 = ks * 8 + 2 * qid;
            unsigned afr[4][4];
            unsigned bfr[4][2];
            #pragma unroll
            for (int mt = 0; mt < 4; mt++) {
                int r0 = wm * 64 + mt * 16 + gid;
                uint2 lo = *(const uint2*)&Ab[swz(r0, c0)];
                uint2 hi = *(const uint2*)&Ab[swz(r0 + 8, c0)];
                afr[mt][0] = lo.x; afr[mt][2] = lo.y;
                afr[mt][1] = hi.x; afr[mt][3] = hi.y;
            }
            #pragma unroll
            for (int nt = 0; nt < 4; nt++) {
                int rn = wn * 32 + nt * 8 + gid;
                uint2 bb = *(const uint2*)&Wb[swz(rn, c0)];
                bfr[nt][0] = bb.x; bfr[nt][1] = bb.y;
            }
            #pragma unroll
            for (int mt = 0; mt < 4; mt++)
                #pragma unroll
                for (int nt = 0; nt < 4; nt++) {
                    asm volatile(
                        "mma.sync.aligned.m16n8k8.row.col.f32.tf32.tf32.f32 "
                        "{%0,%1,%2,%3}, {%4,%5,%6,%7}, {%8,%9}, {%0,%1,%2,%3};\n"
                        : "+f"(cacc[mt][nt][0]), "+f"(cacc[mt][nt][1]),
                          "+f"(cacc[mt][nt][2]), "+f"(cacc[mt][nt][3])
                        : "r"(afr[mt][0]), "r"(afr[mt][1]),
                          "r"(afr[mt][2]), "r"(afr[mt][3]),
                          "r"(bfr[nt][0]), "r"(bfr[nt][1]));
                }
        }
        __syncthreads();
        if (ch + 2 < nchunks) issue(ch + 2, s);
        CP_COMMIT();
    }

    #pragma unroll
    for (int mt = 0; mt < 4; mt++) {
        int row = bm + wm * 64 + mt * 16 + gid;
        #pragma unroll
        for (int nt = 0; nt < 4; nt++) {
            int col = bn + wn * 32 + nt * 8 + qid * 2;
            *(float2*)(C + (size_t)row * N + col) =
                make_float2(cacc[mt][nt][0], cacc[mt][nt][1]);
            *(float2*)(C + (size_t)(row + 8) * N + col) =
                make_float2(cacc[mt][nt][2], cacc[mt][nt][3]);
        }
    }
}

// ---------------- classifier heads on cls token (b, 0) ----------------
__global__ void heads_k(const float* __restrict__ xn,
                        const float* __restrict__ rw, const float* __restrict__ rb,
                        const float* __restrict__ mw, const float* __restrict__ mb,
                        float* __restrict__ out) {
    int b = blockIdx.x;
    int t = threadIdx.x;
    float xv = xn[((size_t)b * L_) * D_ + t];
    float pr = xv * rw[t];
    float pm = xv * mw[t];
    __shared__ float sr[8], sm_[8];
    #pragma unroll
    for (int o = 16; o; o >>= 1) {
        pr += __shfl_xor_sync(0xFFFFFFFFu, pr, o);
        pm += __shfl_xor_sync(0xFFFFFFFFu, pm, o);
    }
    if ((t & 31) == 0) { sr[t >> 5] = pr; sm_[t >> 5] = pm; }
    __syncthreads();
    if (t == 0) {
        float a = 0.0f, c = 0.0f;
        #pragma unroll
        for (int i = 0; i < 8; i++) { a += sr[i]; c += sm_[i]; }
        out[b]      = a + rb[0];
        out[B_ + b] = c + mb[0];
    }
}

// ---------------- driver ----------------
extern "C" void kernel_launch(void* const* d_in, const int* in_sizes, int n_in,
                              void* d_out, int out_size) {
    const int*   token_ids    = (const int*)  d_in[0];
    const int*   token_types  = (const int*)  d_in[1];
    const int*   amask        = (const int*)  d_in[2];
    const float* tok_emb      = (const float*)d_in[3];
    const float* type_emb     = (const float*)d_in[4];
    const float* norm1_w      = (const float*)d_in[5];
    const float* wq           = (const float*)d_in[6];
    const float* wk           = (const float*)d_in[7];
    const float* wv           = (const float*)d_in[8];
    const float* wo           = (const float*)d_in[9];
    const float* norm2_w      = (const float*)d_in[10];
    const float* ff_w1        = (const float*)d_in[11];
    const float* ff_w2        = (const float*)d_in[12];
    const float* final_norm_w = (const float*)d_in[13];
    const float* lm_w         = (const float*)d_in[14];
    const float* read_w       = (const float*)d_in[15];
    const float* read_b       = (const float*)d_in[16];
    const float* mort_w       = (const float*)d_in[17];
    const float* mort_b       = (const float*)d_in[18];
    float* out = (float*)d_out;

    float *x, *xn, *q, *k, *v, *at, *ff;
    unsigned *a32, *w32;
    cudaGetSymbolAddress((void**)&x,   g_x);
    cudaGetSymbolAddress((void**)&xn,  g_xn);
    cudaGetSymbolAddress((void**)&q,   g_q);
    cudaGetSymbolAddress((void**)&k,   g_k);
    cudaGetSymbolAddress((void**)&v,   g_v);
    cudaGetSymbolAddress((void**)&at,  g_at);
    cudaGetSymbolAddress((void**)&ff,  g_ff);
    cudaGetSymbolAddress((void**)&a32, g_a32);
    cudaGetSymbolAddress((void**)&w32, g_w32);

    cudaFuncSetAttribute(lm_tf32, cudaFuncAttributeMaxDynamicSharedMemorySize, 65536);

    embed_k<<<MTOK * D_ / 256, 256>>>(token_ids, token_types, tok_emb, type_emb, x);

    dim3 gqkv(D_ / 64, MTOK / 128);
    dim3 gqkv3(3 * D_ / 64, MTOK / 128);
    dim3 gff1(FF_ / 64, MTOK / 128);
    for (int li = 0; li < NL_; li++) {
        rms_k<<<MTOK, 256>>>(x, norm1_w + li * D_, xn);
        gemm_qkv<<<gqkv3, 256>>>(xn, wq + (size_t)li * D_ * D_, wk + (size_t)li * D_ * D_,
                                 wv + (size_t)li * D_ * D_, q, k, v, D_);
        rope_k<<<MTOK * H_ * 32 / 256, 256>>>(q, k);
        attn_k<<<dim3(L_ / 128, H_, B_), 128>>>(q, k, v, amask, at);
        gemm_f32<1><<<gqkv, 256>>>(at, wo + (size_t)li * D_ * D_, x, x, MTOK, D_, D_);
        rms_k<<<MTOK, 256>>>(x, norm2_w + li * D_, xn);
        gemm_f32<2><<<gff1, 256>>>(xn, ff_w1 + (size_t)li * FF_ * D_, nullptr, ff, MTOK, FF_, D_);
        gemm_f32<1><<<gqkv, 256>>>(ff, ff_w2 + (size_t)li * D_ * FF_, x, x, MTOK, D_, FF_);
    }
    rms_k<<<MTOK, 256>>>(x, final_norm_w, xn);
    cvt_tf32_perm<<<MTOK * D_ / 256, 256>>>(xn, a32);
    cvt_tf32_perm<<<V_ * D_ / 256, 256>>>(lm_w, w32);
    lm_tf32<<<dim3(V_ / 128, MTOK / 128), 256, 65536>>>(a32, w32, out, MTOK, V_, D_);
    heads_k<<<B_, 256>>>(xn, read_w, read_b, mort_w, mort_b, out + (size_t)MTOK * V_);
}

// round 11
// speedup vs baseline: 1.2751x; 1.0026x over previous
#include <cuda_runtime.h>
#include <math.h>
#include <stdint.h>

#define B_   4
#define L_   2048
#define D_   256
#define H_   4
#define NL_  4
#define V_   32000
#define DH_  64
#define FF_  (4*D_)
#define MTOK (B_*L_)

// ---------------- scratch (allocation-free: __device__ globals) ----------------
__device__ float g_x [MTOK*D_];
__device__ float g_xn[MTOK*D_];
__device__ float g_q [MTOK*D_];
__device__ float g_k [MTOK*D_];
__device__ float g_v [MTOK*D_];
__device__ float g_at[MTOK*D_];
__device__ float g_ff[MTOK*FF_];
__device__ unsigned g_a32[MTOK*D_];              // tf32, k-permuted
__device__ unsigned g_w32[(size_t)V_*D_];        // tf32, k-permuted

// ---------------- embedding ----------------
__global__ void embed_k(const int* __restrict__ ids, const int* __restrict__ tys,
                        const float* __restrict__ tok_emb, const float* __restrict__ type_emb,
                        float* __restrict__ x) {
    int i = blockIdx.x * 256 + threadIdx.x;
    int t = i / D_, d = i - t * D_;
    x[i] = tok_emb[(size_t)ids[t] * D_ + d] + type_emb[tys[t] * D_ + d];
}

// ---------------- RMSNorm ----------------
__global__ void rms_k(const float* __restrict__ x, const float* __restrict__ w,
                      float* __restrict__ y) {
    int row = blockIdx.x;
    int d = threadIdx.x;
    float v = x[(size_t)row * D_ + d];
    float s = v * v;
    __shared__ float sh[8];
    #pragma unroll
    for (int o = 16; o; o >>= 1) s += __shfl_xor_sync(0xFFFFFFFFu, s, o);
    if ((threadIdx.x & 31) == 0) sh[threadIdx.x >> 5] = s;
    __syncthreads();
    if (threadIdx.x < 8) {
        float t = sh[threadIdx.x];
        #pragma unroll
        for (int o = 4; o; o >>= 1) t += __shfl_xor_sync(0xFFu, t, o);
        if (threadIdx.x == 0) sh[0] = t;
    }
    __syncthreads();
    float mean = sh[0] * (1.0f / D_);
    float r = rsqrtf(mean + 1.1920929e-07f);
    y[(size_t)row * D_ + d] = v * r * w[d];
}

// ---------------- RoPE ----------------
__global__ void rope_k(float* __restrict__ q, float* __restrict__ k) {
    int i = blockIdx.x * 256 + threadIdx.x;
    int j  = i & 31;
    int hh = (i >> 5) & (H_ - 1);
    int t  = i >> 7;
    int pos = t & (L_ - 1);
    float freq = expf(-logf(10000.0f) * (float)j * (1.0f / 32.0f));
    float ang = (float)pos * freq;
    float c = cosf(ang), s = sinf(ang);
    size_t base = (size_t)t * D_ + hh * DH_ + j;
    float q0 = q[base], q1 = q[base + 32];
    q[base]      = q0 * c - q1 * s;
    q[base + 32] = q1 * c + q0 * s;
    float k0 = k[base], k1 = k[base + 32];
    k[base]      = k0 * c - k1 * s;
    k[base + 32] = k1 * c + k0 * s;
}

// ---------------- flash-style causal attention ----------------
// 128 threads, one query per thread, 2 keys per inner iteration for ILP.
__global__ void __launch_bounds__(128) attn_k(const float* __restrict__ q,
                                              const float* __restrict__ k,
                                              const float* __restrict__ v,
                                              const int* __restrict__ am,
                                              float* __restrict__ out) {
    int qt = gridDim.x - 1 - blockIdx.x;
    int h = blockIdx.y, b = blockIdx.z;
    int qrow = qt * 128 + threadIdx.x;
    __shared__ float Ks[64][64];
    __shared__ float Vs[64][64];
    __shared__ int   Ms[64];

    float qr[64];
    size_t qbase = ((size_t)(b * L_ + qrow)) * D_ + h * DH_;
    #pragma unroll
    for (int d = 0; d < 64; d++) qr[d] = q[qbase + d] * 0.125f;

    float m = -1e30f, l = 0.0f;
    float acc[64];
    #pragma unroll
    for (int d = 0; d < 64; d++) acc[d] = 0.0f;

    int ntiles = 2 * qt + 2;
    for (int kt = 0; kt < ntiles; kt++) {
        int krow0 = kt * 64;
        {
            int r = threadIdx.x >> 1, half = (threadIdx.x & 1) * 32;
            size_t gb = ((size_t)(b * L_ + krow0 + r)) * D_ + h * DH_ + half;
            float4*       Kd = (float4*)&Ks[r][half];
            const float4* Kg = (const float4*)(k + gb);
            float4*       Vd = (float4*)&Vs[r][half];
            const float4* Vg = (const float4*)(v + gb);
            #pragma unroll
            for (int u = 0; u < 8; u++) { Kd[u] = Kg[u]; Vd[u] = Vg[u]; }
            if (threadIdx.x < 64) Ms[threadIdx.x] = am[b * L_ + krow0 + threadIdx.x];
        }
        __syncthreads();
        int klim = qrow - krow0 + 1;
        if (klim > 64) klim = 64;
        int kk = 0;
        for (; kk + 1 < klim; kk += 2) {
            const float* K0 = Ks[kk];
            const float* K1 = Ks[kk + 1];
            float a0 = 0.f, b0 = 0.f, a1 = 0.f, b1 = 0.f;
            #pragma unroll
            for (int d = 0; d < 64; d += 2) {
                a0 += qr[d]     * K0[d];
                b0 += qr[d + 1] * K0[d + 1];
                a1 += qr[d]     * K1[d];
                b1 += qr[d + 1] * K1[d + 1];
            }
            float s0 = Ms[kk]     ? (a0 + b0) : -1e30f;
            float s1 = Ms[kk + 1] ? (a1 + b1) : -1e30f;
            float sm = fmaxf(s0, s1);
            if (sm > m) {
                float c0 = __expf(m - sm);
                l *= c0;
                #pragma unroll
                for (int d = 0; d < 64; d++) acc[d] *= c0;
                m = sm;
            }
            float p0 = (s0 > -1e29f) ? __expf(s0 - m) : 0.0f;
            float p1 = (s1 > -1e29f) ? __expf(s1 - m) : 0.0f;
            l += p0 + p1;
            const float* V0 = Vs[kk];
            const float* V1 = Vs[kk + 1];
            #pragma unroll
            for (int d = 0; d < 64; d++) acc[d] += p0 * V0[d] + p1 * V1[d];
        }
        if (kk < klim && Ms[kk]) {                 // odd tail key
            const float* K0 = Ks[kk];
            float a0 = 0.f, b0 = 0.f, c0p = 0.f, d0 = 0.f;
            #pragma unroll
            for (int d = 0; d < 64; d += 4) {
                a0  += qr[d]     * K0[d];
                b0  += qr[d + 1] * K0[d + 1];
                c0p += qr[d + 2] * K0[d + 2];
                d0  += qr[d + 3] * K0[d + 3];
            }
            float s = (a0 + b0) + (c0p + d0);
            if (s > m) {
                float c0 = __expf(m - s);
                l *= c0;
                #pragma unroll
                for (int d = 0; d < 64; d++) acc[d] *= c0;
                m = s;
            }
            float p = __expf(s - m);
            l += p;
            const float* V0 = Vs[kk];
            #pragma unroll
            for (int d = 0; d < 64; d++) acc[d] += p * V0[d];
        }
        __syncthreads();
    }
    float inv = (l > 0.0f) ? (1.0f / l) : 0.0f;
    #pragma unroll
    for (int d = 0; d < 64; d++) out[qbase + d] = acc[d] * inv;
}

// ---------------- fp32 GEMM body (layer path, exact; R8-proven) ----------------
template <int EPI>
__device__ __forceinline__ void gemm_body(const float* __restrict__ A,
                                          const float* __restrict__ W,
                                          const float* __restrict__ R,
                                          float* __restrict__ C,
                                          int N, int K, int bm, int bn) {
    __shared__ __align__(16) float As[2][16][132];
    __shared__ __align__(16) float Ws[2][16][68];
    const int tid = threadIdx.x;
    const int tx = tid & 15, ty = tid >> 4;
    const int arow = tid >> 2;
    const int k4 = (tid & 3) << 2;
    const float* Ap0 = A + (size_t)(bm + arow) * K + k4;
    const float* Ap1 = A + (size_t)(bm + arow + 64) * K + k4;
    const float* Wp  = W + (size_t)(bn + arow) * K + k4;

    float acc[8][4];
    #pragma unroll
    for (int i = 0; i < 8; i++)
        #pragma unroll
        for (int j = 0; j < 4; j++) acc[i][j] = 0.0f;

    float4 pa0 = *(const float4*)Ap0;
    float4 pa1 = *(const float4*)Ap1;
    float4 pw  = *(const float4*)Wp;
    {
        float a0[4] = {pa0.x, pa0.y, pa0.z, pa0.w};
        float a1[4] = {pa1.x, pa1.y, pa1.z, pa1.w};
        float w0[4] = {pw.x,  pw.y,  pw.z,  pw.w};
        #pragma unroll
        for (int j = 0; j < 4; j++) {
            As[0][k4 + j][arow]      = a0[j];
            As[0][k4 + j][arow + 64] = a1[j];
            Ws[0][k4 + j][arow]      = w0[j];
        }
    }
    __syncthreads();

    const int nch = K >> 4;
    for (int ch = 0; ch < nch; ch++) {
        const int s = ch & 1;
        if (ch + 1 < nch) {
            pa0 = *(const float4*)(Ap0 + (ch + 1) * 16);
            pa1 = *(const float4*)(Ap1 + (ch + 1) * 16);
            pw  = *(const float4*)(Wp  + (ch + 1) * 16);
        }
        #pragma unroll
        for (int kk = 0; kk < 16; kk++) {
            float4 av0 = *(const float4*)&As[s][kk][ty * 8];
            float4 av1 = *(const float4*)&As[s][kk][ty * 8 + 4];
            float4 wv  = *(const float4*)&Ws[s][kk][tx * 4];
            float a[8] = {av0.x, av0.y, av0.z, av0.w, av1.x, av1.y, av1.z, av1.w};
            float w[4] = {wv.x, wv.y, wv.z, wv.w};
            #pragma unroll
            for (int i = 0; i < 8; i++)
                #pragma unroll
                for (int j = 0; j < 4; j++) acc[i][j] += a[i] * w[j];
        }
        if (ch + 1 < nch) {
            const int s2 = (ch + 1) & 1;
            float a0[4] = {pa0.x, pa0.y, pa0.z, pa0.w};
            float a1[4] = {pa1.x, pa1.y, pa1.z, pa1.w};
            float w0[4] = {pw.x,  pw.y,  pw.z,  pw.w};
            #pragma unroll
            for (int j = 0; j < 4; j++) {
                As[s2][k4 + j][arow]      = a0[j];
                As[s2][k4 + j][arow + 64] = a1[j];
                Ws[s2][k4 + j][arow]      = w0[j];
            }
        }
        __syncthreads();
    }

    #pragma unroll
    for (int i = 0; i < 8; i++) {
        size_t idx = (size_t)(bm + ty * 8 + i) * N + bn + tx * 4;
        float4 vv = make_float4(acc[i][0], acc[i][1], acc[i][2], acc[i][3]);
        if (EPI == 1) {
            float4 rr = *(const float4*)(R + idx);
            vv.x += rr.x; vv.y += rr.y; vv.z += rr.z; vv.w += rr.w;
        }
        if (EPI == 2) {
            vv.x = vv.x / (1.0f + expf(-vv.x));
            vv.y = vv.y / (1.0f + expf(-vv.y));
            vv.z = vv.z / (1.0f + expf(-vv.z));
            vv.w = vv.w / (1.0f + expf(-vv.w));
        }
        *(float4*)(C + idx) = vv;
    }
}

template <int EPI>
__global__ void __launch_bounds__(256) gemm_f32(const float* __restrict__ A,
                                                const float* __restrict__ W,
                                                const float* __restrict__ R,
                                                float* __restrict__ C,
                                                int M, int N, int K) {
    gemm_body<EPI>(A, W, R, C, N, K, blockIdx.y * 128, blockIdx.x * 64);
}

// fused Q/K/V projection: one launch, blockIdx.x selects matrix + n-tile
__global__ void __launch_bounds__(256) gemm_qkv(const float* __restrict__ A,
                                                const float* __restrict__ Wq,
                                                const float* __restrict__ Wk,
                                                const float* __restrict__ Wv,
                                                float* __restrict__ q,
                                                float* __restrict__ kk,
                                                float* __restrict__ vv,
                                                int K) {
    int sel = blockIdx.x >> 2;
    const float* W = (sel == 0) ? Wq : (sel == 1) ? Wk : Wv;
    float*       C = (sel == 0) ? q  : (sel == 1) ? kk : vv;
    gemm_body<0>(A, W, nullptr, C, D_, K, blockIdx.y * 128, (blockIdx.x & 3) * 64);
}

// ---------------- tf32 helpers ----------------
__device__ __forceinline__ unsigned f2tf32(float v) {
    unsigned o;
    asm("cvt.rna.tf32.f32 %0, %1;" : "=r"(o) : "f"(v));
    return o;
}
__device__ __forceinline__ int kperm(int kl) {   // kl in [0,32)
    return (kl & ~7) | ((kl & 3) << 1) | ((kl & 4) >> 2);
}
__device__ __forceinline__ int swz(int row, int col) {
    return row * 32 + (col ^ ((row & 3) << 3));
}
__device__ __forceinline__ uint32_t smem_u32(const void* p) {
    uint32_t a;
    asm("{ .reg .u64 t; cvta.to.shared.u64 t, %1; cvt.u32.u64 %0, t; }" : "=r"(a) : "l"(p));
    return a;
}
#define CP_ASYNC16(dst_u32, src_ptr) \
    asm volatile("cp.async.cg.shared.global [%0], [%1], 16;" :: "r"(dst_u32), "l"(src_ptr))
#define CP_COMMIT() asm volatile("cp.async.commit_group;" ::: "memory")
#define CP_WAIT1()  asm volatile("cp.async.wait_group 1;" ::: "memory")

// fp32 -> tf32-rounded + k-permuted (permutation stays within a 32-elem window)
__global__ void cvt_tf32_perm(const float* __restrict__ x, unsigned* __restrict__ o) {
    int i = blockIdx.x * 256 + threadIdx.x;
    int kl = i & 31;
    o[(i & ~31) | kperm(kl)] = f2tf32(x[i]);
}

// ---------------- tf32 mma.sync GEMM, 3-stage cp.async pipeline (LM head) ----------------
// __launch_bounds__(256, 2): 2 CTAs/SM. Stage ring of 3: two chunks in flight
// during MMA compute (issue for ch+2 happens BEFORE compute of ch).
__global__ void __launch_bounds__(256, 2) lm_tf32(const unsigned* __restrict__ A,
                                                  const unsigned* __restrict__ W,
                                                  float* __restrict__ C,
                                                  int M, int N, int K) {
    extern __shared__ unsigned sbuf[];            // 3 stages x (A 4096 | W 4096)
    const uint32_t sb = smem_u32(sbuf);

    const int bm = blockIdx.y * 128, bn = blockIdx.x * 128;
    const int tid = threadIdx.x;
    const int warp = tid >> 5, lane = tid & 31;
    const int wm = warp >> 2, wn = warp & 3;
    const int gid = lane >> 2, qid = lane & 3;
    const int nchunks = K >> 5;

    auto issue = [&](int ch, int s) {
        const uint32_t abase = (uint32_t)(s * 8192) * 4u;
        const uint32_t wbase = abase + 4096u * 4u;
        #pragma unroll
        for (int t = 0; t < 4; t++) {
            int c2 = tid + t * 256;
            int row = c2 >> 3, col4 = (c2 & 7) << 2;
            uint32_t so = (uint32_t)swz(row, col4) * 4u;
            const unsigned* ga = A + (size_t)(bm + row) * K + ch * 32 + col4;
            const unsigned* gw = W + (size_t)(bn + row) * K + ch * 32 + col4;
            CP_ASYNC16(sb + abase + so, ga);
            CP_ASYNC16(sb + wbase + so, gw);
        }
    };

    float cacc[4][4][4];
    #pragma unroll
    for (int i = 0; i < 4; i++)
        #pragma unroll
        for (int j = 0; j < 4; j++)
            #pragma unroll
            for (int f = 0; f < 4; f++) cacc[i][j][f] = 0.0f;

    issue(0, 0); CP_COMMIT();
    issue(1, 1); CP_COMMIT();

    for (int ch = 0; ch < nchunks; ch++) {
        const int s = ch % 3;
        CP_WAIT1();                               // group ch complete
        __syncthreads();                          // all threads past compute(ch-1)
        if (ch + 2 < nchunks) {                   // refill buffer (ch+2)%3 = (ch-1)%3
            issue(ch + 2, (ch + 2) % 3);
            CP_COMMIT();
        }
        const unsigned* Ab = sbuf + s * 8192;
        const unsigned* Wb = Ab + 4096;
        #pragma unroll
        for (int ks = 0; ks < 4; ks++) {
            const int c0 = ks * 8 + 2 * qid;
            unsigned afr[4][4];
            unsigned bfr[4][2];
            #pragma unroll
            for (int mt = 0; mt < 4; mt++) {
                int r0 = wm * 64 + mt * 16 + gid;
                uint2 lo = *(const uint2*)&Ab[swz(r0, c0)];
                uint2 hi = *(const uint2*)&Ab[swz(r0 + 8, c0)];
                afr[mt][0] = lo.x; afr[mt][2] = lo.y;
                afr[mt][1] = hi.x; afr[mt][3] = hi.y;
            }
            #pragma unroll
            for (int nt = 0; nt < 4; nt++) {
                int rn = wn * 32 + nt * 8 + gid;
                uint2 bb = *(const uint2*)&Wb[swz(rn, c0)];
                bfr[nt][0] = bb.x; bfr[nt][1] = bb.y;
            }
            #pragma unroll
            for (int mt = 0; mt < 4; mt++)
                #pragma unroll
                for (int nt = 0; nt < 4; nt++) {
                    asm volatile(
                        "mma.sync.aligned.m16n8k8.row.col.f32.tf32.tf32.f32 "
                        "{%0,%1,%2,%3}, {%4,%5,%6,%7}, {%8,%9}, {%0,%1,%2,%3};\n"
                        : "+f"(cacc[mt][nt][0]), "+f"(cacc[mt][nt][1]),
                          "+f"(cacc[mt][nt][2]), "+f"(cacc[mt][nt][3])
                        : "r"(afr[mt][0]), "r"(afr[mt][1]),
                          "r"(afr[mt][2]), "r"(afr[mt][3]),
                          "r"(bfr[nt][0]), "r"(bfr[nt][1]));
                }
        }
    }

    #pragma unroll
    for (int mt = 0; mt < 4; mt++) {
        int row = bm + wm * 64 + mt * 16 + gid;
        #pragma unroll
        for (int nt = 0; nt < 4; nt++) {
            int col = bn + wn * 32 + nt * 8 + qid * 2;
            *(float2*)(C + (size_t)row * N + col) =
                make_float2(cacc[mt][nt][0], cacc[mt][nt][1]);
            *(float2*)(C + (size_t)(row + 8) * N + col) =
                make_float2(cacc[mt][nt][2], cacc[mt][nt][3]);
        }
    }
}

// ---------------- classifier heads on cls token (b, 0) ----------------
__global__ void heads_k(const float* __restrict__ xn,
                        const float* __restrict__ rw, const float* __restrict__ rb,
                        const float* __restrict__ mw, const float* __restrict__ mb,
                        float* __restrict__ out) {
    int b = blockIdx.x;
    int t = threadIdx.x;
    float xv = xn[((size_t)b * L_) * D_ + t];
    float pr = xv * rw[t];
    float pm = xv * mw[t];
    __shared__ float sr[8], sm_[8];
    #pragma unroll
    for (int o = 16; o; o >>= 1) {
        pr += __shfl_xor_sync(0xFFFFFFFFu, pr, o);
        pm += __shfl_xor_sync(0xFFFFFFFFu, pm, o);
    }
    if ((t & 31) == 0) { sr[t >> 5] = pr; sm_[t >> 5] = pm; }
    __syncthreads();
    if (t == 0) {
        float a = 0.0f, c = 0.0f;
        #pragma unroll
        for (int i = 0; i < 8; i++) { a += sr[i]; c += sm_[i]; }
        out[b]      = a + rb[0];
        out[B_ + b] = c + mb[0];
    }
}

// ---------------- driver ----------------
extern "C" void kernel_launch(void* const* d_in, const int* in_sizes, int n_in,
                              void* d_out, int out_size) {
    const int*   token_ids    = (const int*)  d_in[0];
    const int*   token_types  = (const int*)  d_in[1];
    const int*   amask        = (const int*)  d_in[2];
    const float* tok_emb      = (const float*)d_in[3];
    const float* type_emb     = (const float*)d_in[4];
    const float* norm1_w      = (const float*)d_in[5];
    const float* wq           = (const float*)d_in[6];
    const float* wk           = (const float*)d_in[7];
    const float* wv           = (const float*)d_in[8];
    const float* wo           = (const float*)d_in[9];
    const float* norm2_w      = (const float*)d_in[10];
    const float* ff_w1        = (const float*)d_in[11];
    const float* ff_w2        = (const float*)d_in[12];
    const float* final_norm_w = (const float*)d_in[13];
    const float* lm_w         = (const float*)d_in[14];
    const float* read_w       = (const float*)d_in[15];
    const float* read_b       = (const float*)d_in[16];
    const float* mort_w       = (const float*)d_in[17];
    const float* mort_b       = (const float*)d_in[18];
    float* out = (float*)d_out;

    float *x, *xn, *q, *k, *v, *at, *ff;
    unsigned *a32, *w32;
    cudaGetSymbolAddress((void**)&x,   g_x);
    cudaGetSymbolAddress((void**)&xn,  g_xn);
    cudaGetSymbolAddress((void**)&q,   g_q);
    cudaGetSymbolAddress((void**)&k,   g_k);
    cudaGetSymbolAddress((void**)&v,   g_v);
    cudaGetSymbolAddress((void**)&at,  g_at);
    cudaGetSymbolAddress((void**)&ff,  g_ff);
    cudaGetSymbolAddress((void**)&a32, g_a32);
    cudaGetSymbolAddress((void**)&w32, g_w32);

    cudaFuncSetAttribute(lm_tf32, cudaFuncAttributeMaxDynamicSharedMemorySize, 98304);

    embed_k<<<MTOK * D_ / 256, 256>>>(token_ids, token_types, tok_emb, type_emb, x);

    dim3 gqkv(D_ / 64, MTOK / 128);
    dim3 gqkv3(3 * D_ / 64, MTOK / 128);
    dim3 gff1(FF_ / 64, MTOK / 128);
    for (int li = 0; li < NL_; li++) {
        rms_k<<<MTOK, 256>>>(x, norm1_w + li * D_, xn);
        gemm_qkv<<<gqkv3, 256>>>(xn, wq + (size_t)li * D_ * D_, wk + (size_t)li * D_ * D_,
                                 wv + (size_t)li * D_ * D_, q, k, v, D_);
        rope_k<<<MTOK * H_ * 32 / 256, 256>>>(q, k);
        attn_k<<<dim3(L_ / 128, H_, B_), 128>>>(q, k, v, amask, at);
        gemm_f32<1><<<gqkv, 256>>>(at, wo + (size_t)li * D_ * D_, x, x, MTOK, D_, D_);
        rms_k<<<MTOK, 256>>>(x, norm2_w + li * D_, xn);
        gemm_f32<2><<<gff1, 256>>>(xn, ff_w1 + (size_t)li * FF_ * D_, nullptr, ff, MTOK, FF_, D_);
        gemm_f32<1><<<gqkv, 256>>>(ff, ff_w2 + (size_t)li * D_ * FF_, x, x, MTOK, D_, FF_);
    }
    rms_k<<<MTOK, 256>>>(x, final_norm_w, xn);
    cvt_tf32_perm<<<MTOK * D_ / 256, 256>>>(xn, a32);
    cvt_tf32_perm<<<V_ * D_ / 256, 256>>>(lm_w, w32);
    lm_tf32<<<dim3(V_ / 128, MTOK / 128), 256, 98304>>>(a32, w32, out, MTOK, V_, D_);
    heads_k<<<B_, 256>>>(xn, read_w, read_b, mort_w, mort_b, out + (size_t)MTOK * V_);
}

// round 12
// speedup vs baseline: 1.3675x; 1.0724x over previous
#include <cuda_runtime.h>
#include <cuda_fp16.h>
#include <math.h>
#include <stdint.h>

#define B_   4
#define L_   2048
#define D_   256
#define H_   4
#define NL_  4
#define V_   32000
#define DH_  64
#define FF_  (4*D_)
#define MTOK (B_*L_)

// ---------------- scratch (allocation-free: __device__ globals) ----------------
__device__ float g_x [MTOK*D_];
__device__ float g_xn[MTOK*D_];
__device__ float g_q [MTOK*D_];
__device__ float g_k [MTOK*D_];
__device__ float g_v [MTOK*D_];
__device__ float g_at[MTOK*D_];
__device__ float g_ff[MTOK*FF_];
__device__ __half g_a16[MTOK*D_];                // fp16, pair-permuted
__device__ __half g_w16[(size_t)V_*D_];          // fp16, pair-permuted

// ---------------- embedding ----------------
__global__ void embed_k(const int* __restrict__ ids, const int* __restrict__ tys,
                        const float* __restrict__ tok_emb, const float* __restrict__ type_emb,
                        float* __restrict__ x) {
    int i = blockIdx.x * 256 + threadIdx.x;
    int t = i / D_, d = i - t * D_;
    x[i] = tok_emb[(size_t)ids[t] * D_ + d] + type_emb[tys[t] * D_ + d];
}

// ---------------- RMSNorm ----------------
__global__ void rms_k(const float* __restrict__ x, const float* __restrict__ w,
                      float* __restrict__ y) {
    int row = blockIdx.x;
    int d = threadIdx.x;
    float v = x[(size_t)row * D_ + d];
    float s = v * v;
    __shared__ float sh[8];
    #pragma unroll
    for (int o = 16; o; o >>= 1) s += __shfl_xor_sync(0xFFFFFFFFu, s, o);
    if ((threadIdx.x & 31) == 0) sh[threadIdx.x >> 5] = s;
    __syncthreads();
    if (threadIdx.x < 8) {
        float t = sh[threadIdx.x];
        #pragma unroll
        for (int o = 4; o; o >>= 1) t += __shfl_xor_sync(0xFFu, t, o);
        if (threadIdx.x == 0) sh[0] = t;
    }
    __syncthreads();
    float mean = sh[0] * (1.0f / D_);
    float r = rsqrtf(mean + 1.1920929e-07f);
    y[(size_t)row * D_ + d] = v * r * w[d];
}

// ---------------- RoPE ----------------
__global__ void rope_k(float* __restrict__ q, float* __restrict__ k) {
    int i = blockIdx.x * 256 + threadIdx.x;
    int j  = i & 31;
    int hh = (i >> 5) & (H_ - 1);
    int t  = i >> 7;
    int pos = t & (L_ - 1);
    float freq = expf(-logf(10000.0f) * (float)j * (1.0f / 32.0f));
    float ang = (float)pos * freq;
    float c = cosf(ang), s = sinf(ang);
    size_t base = (size_t)t * D_ + hh * DH_ + j;
    float q0 = q[base], q1 = q[base + 32];
    q[base]      = q0 * c - q1 * s;
    q[base + 32] = q1 * c + q0 * s;
    float k0 = k[base], k1 = k[base + 32];
    k[base]      = k0 * c - k1 * s;
    k[base + 32] = k1 * c + k0 * s;
}

// ---------------- flash-style causal attention (R11 form) ----------------
__global__ void __launch_bounds__(128) attn_k(const float* __restrict__ q,
                                              const float* __restrict__ k,
                                              const float* __restrict__ v,
                                              const int* __restrict__ am,
                                              float* __restrict__ out) {
    int qt = gridDim.x - 1 - blockIdx.x;
    int h = blockIdx.y, b = blockIdx.z;
    int qrow = qt * 128 + threadIdx.x;
    __shared__ float Ks[64][64];
    __shared__ float Vs[64][64];
    __shared__ int   Ms[64];

    float qr[64];
    size_t qbase = ((size_t)(b * L_ + qrow)) * D_ + h * DH_;
    #pragma unroll
    for (int d = 0; d < 64; d++) qr[d] = q[qbase + d] * 0.125f;

    float m = -1e30f, l = 0.0f;
    float acc[64];
    #pragma unroll
    for (int d = 0; d < 64; d++) acc[d] = 0.0f;

    int ntiles = 2 * qt + 2;
    for (int kt = 0; kt < ntiles; kt++) {
        int krow0 = kt * 64;
        {
            int r = threadIdx.x >> 1, half = (threadIdx.x & 1) * 32;
            size_t gb = ((size_t)(b * L_ + krow0 + r)) * D_ + h * DH_ + half;
            float4*       Kd = (float4*)&Ks[r][half];
            const float4* Kg = (const float4*)(k + gb);
            float4*       Vd = (float4*)&Vs[r][half];
            const float4* Vg = (const float4*)(v + gb);
            #pragma unroll
            for (int u = 0; u < 8; u++) { Kd[u] = Kg[u]; Vd[u] = Vg[u]; }
            if (threadIdx.x < 64) Ms[threadIdx.x] = am[b * L_ + krow0 + threadIdx.x];
        }
        __syncthreads();
        int klim = qrow - krow0 + 1;
        if (klim > 64) klim = 64;
        int kk = 0;
        for (; kk + 1 < klim; kk += 2) {
            const float* K0 = Ks[kk];
            const float* K1 = Ks[kk + 1];
            float a0 = 0.f, b0 = 0.f, a1 = 0.f, b1 = 0.f;
            #pragma unroll
            for (int d = 0; d < 64; d += 2) {
                a0 += qr[d]     * K0[d];
                b0 += qr[d + 1] * K0[d + 1];
                a1 += qr[d]     * K1[d];
                b1 += qr[d + 1] * K1[d + 1];
            }
            float s0 = Ms[kk]     ? (a0 + b0) : -1e30f;
            float s1 = Ms[kk + 1] ? (a1 + b1) : -1e30f;
            float sm = fmaxf(s0, s1);
            if (sm > m) {
                float c0 = __expf(m - sm);
                l *= c0;
                #pragma unroll
                for (int d = 0; d < 64; d++) acc[d] *= c0;
                m = sm;
            }
            float p0 = (s0 > -1e29f) ? __expf(s0 - m) : 0.0f;
            float p1 = (s1 > -1e29f) ? __expf(s1 - m) : 0.0f;
            l += p0 + p1;
            const float* V0 = Vs[kk];
            const float* V1 = Vs[kk + 1];
            #pragma unroll
            for (int d = 0; d < 64; d++) acc[d] += p0 * V0[d] + p1 * V1[d];
        }
        if (kk < klim && Ms[kk]) {
            const float* K0 = Ks[kk];
            float a0 = 0.f, b0 = 0.f, c0p = 0.f, d0 = 0.f;
            #pragma unroll
            for (int d = 0; d < 64; d += 4) {
                a0  += qr[d]     * K0[d];
                b0  += qr[d + 1] * K0[d + 1];
                c0p += qr[d + 2] * K0[d + 2];
                d0  += qr[d + 3] * K0[d + 3];
            }
            float s = (a0 + b0) + (c0p + d0);
            if (s > m) {
                float c0 = __expf(m - s);
                l *= c0;
                #pragma unroll
                for (int d = 0; d < 64; d++) acc[d] *= c0;
                m = s;
            }
            float p = __expf(s - m);
            l += p;
            const float* V0 = Vs[kk];
            #pragma unroll
            for (int d = 0; d < 64; d++) acc[d] += p * V0[d];
        }
        __syncthreads();
    }
    float inv = (l > 0.0f) ? (1.0f / l) : 0.0f;
    #pragma unroll
    for (int d = 0; d < 64; d++) out[qbase + d] = acc[d] * inv;
}

// ---------------- fp32 GEMM body (layer path, exact; R8-proven) ----------------
template <int EPI>
__device__ __forceinline__ void gemm_body(const float* __restrict__ A,
                                          const float* __restrict__ W,
                                          const float* __restrict__ R,
                                          float* __restrict__ C,
                                          int N, int K, int bm, int bn) {
    __shared__ __align__(16) float As[2][16][132];
    __shared__ __align__(16) float Ws[2][16][68];
    const int tid = threadIdx.x;
    const int tx = tid & 15, ty = tid >> 4;
    const int arow = tid >> 2;
    const int k4 = (tid & 3) << 2;
    const float* Ap0 = A + (size_t)(bm + arow) * K + k4;
    const float* Ap1 = A + (size_t)(bm + arow + 64) * K + k4;
    const float* Wp  = W + (size_t)(bn + arow) * K + k4;

    float acc[8][4];
    #pragma unroll
    for (int i = 0; i < 8; i++)
        #pragma unroll
        for (int j = 0; j < 4; j++) acc[i][j] = 0.0f;

    float4 pa0 = *(const float4*)Ap0;
    float4 pa1 = *(const float4*)Ap1;
    float4 pw  = *(const float4*)Wp;
    {
        float a0[4] = {pa0.x, pa0.y, pa0.z, pa0.w};
        float a1[4] = {pa1.x, pa1.y, pa1.z, pa1.w};
        float w0[4] = {pw.x,  pw.y,  pw.z,  pw.w};
        #pragma unroll
        for (int j = 0; j < 4; j++) {
            As[0][k4 + j][arow]      = a0[j];
            As[0][k4 + j][arow + 64] = a1[j];
            Ws[0][k4 + j][arow]      = w0[j];
        }
    }
    __syncthreads();

    const int nch = K >> 4;
    for (int ch = 0; ch < nch; ch++) {
        const int s = ch & 1;
        if (ch + 1 < nch) {
            pa0 = *(const float4*)(Ap0 + (ch + 1) * 16);
            pa1 = *(const float4*)(Ap1 + (ch + 1) * 16);
            pw  = *(const float4*)(Wp  + (ch + 1) * 16);
        }
        #pragma unroll
        for (int kk = 0; kk < 16; kk++) {
            float4 av0 = *(const float4*)&As[s][kk][ty * 8];
            float4 av1 = *(const float4*)&As[s][kk][ty * 8 + 4];
            float4 wv  = *(const float4*)&Ws[s][kk][tx * 4];
            float a[8] = {av0.x, av0.y, av0.z, av0.w, av1.x, av1.y, av1.z, av1.w};
            float w[4] = {wv.x, wv.y, wv.z, wv.w};
            #pragma unroll
            for (int i = 0; i < 8; i++)
                #pragma unroll
                for (int j = 0; j < 4; j++) acc[i][j] += a[i] * w[j];
        }
        if (ch + 1 < nch) {
            const int s2 = (ch + 1) & 1;
            float a0[4] = {pa0.x, pa0.y, pa0.z, pa0.w};
            float a1[4] = {pa1.x, pa1.y, pa1.z, pa1.w};
            float w0[4] = {pw.x,  pw.y,  pw.z,  pw.w};
            #pragma unroll
            for (int j = 0; j < 4; j++) {
                As[s2][k4 + j][arow]      = a0[j];
                As[s2][k4 + j][arow + 64] = a1[j];
                Ws[s2][k4 + j][arow]      = w0[j];
            }
        }
        __syncthreads();
    }

    #pragma unroll
    for (int i = 0; i < 8; i++) {
        size_t idx = (size_t)(bm + ty * 8 + i) * N + bn + tx * 4;
        float4 vv = make_float4(acc[i][0], acc[i][1], acc[i][2], acc[i][3]);
        if (EPI == 1) {
            float4 rr = *(const float4*)(R + idx);
            vv.x += rr.x; vv.y += rr.y; vv.z += rr.z; vv.w += rr.w;
        }
        if (EPI == 2) {
            vv.x = vv.x / (1.0f + expf(-vv.x));
            vv.y = vv.y / (1.0f + expf(-vv.y));
            vv.z = vv.z / (1.0f + expf(-vv.z));
            vv.w = vv.w / (1.0f + expf(-vv.w));
        }
        *(float4*)(C + idx) = vv;
    }
}

template <int EPI>
__global__ void __launch_bounds__(256) gemm_f32(const float* __restrict__ A,
                                                const float* __restrict__ W,
                                                const float* __restrict__ R,
                                                float* __restrict__ C,
                                                int M, int N, int K) {
    gemm_body<EPI>(A, W, R, C, N, K, blockIdx.y * 128, blockIdx.x * 64);
}

// fused Q/K/V projection: one launch, blockIdx.x selects matrix + n-tile
__global__ void __launch_bounds__(256) gemm_qkv(const float* __restrict__ A,
                                                const float* __restrict__ Wq,
                                                const float* __restrict__ Wk,
                                                const float* __restrict__ Wv,
                                                float* __restrict__ q,
                                                float* __restrict__ kk,
                                                float* __restrict__ vv,
                                                int K) {
    int sel = blockIdx.x >> 2;
    const float* W = (sel == 0) ? Wq : (sel == 1) ? Wk : Wv;
    float*       C = (sel == 0) ? q  : (sel == 1) ? kk : vv;
    gemm_body<0>(A, W, nullptr, C, D_, K, blockIdx.y * 128, (blockIdx.x & 3) * 64);
}

// ---------------- helpers ----------------
__device__ __forceinline__ uint32_t smem_u32(const void* p) {
    uint32_t a;
    asm("{ .reg .u64 t; cvta.to.shared.u64 t, %1; cvt.u32.u64 %0, t; }" : "=r"(a) : "l"(p));
    return a;
}
#define CP_ASYNC16(dst_u32, src_ptr) \
    asm volatile("cp.async.cg.shared.global [%0], [%1], 16;" :: "r"(dst_u32), "l"(src_ptr))
#define CP_COMMIT() asm volatile("cp.async.commit_group;" ::: "memory")
#define CP_WAIT1()  asm volatile("cp.async.wait_group 1;" ::: "memory")

// fp32 -> fp16, pair-permuted within each 32-k window:
// pair p (0..15) -> pos 4*(p&3) + (p>>2), so pairs {q,4+q,8+q,12+q} are one uint4.
__global__ void cvt_f16_perm(const float* __restrict__ x, __half* __restrict__ o) {
    int i = blockIdx.x * 256 + threadIdx.x;
    int k = i & 31;
    int p = (k >> 1) & 15;
    int pos = 4 * (p & 3) + (p >> 2);
    o[(i & ~31) | (pos * 2 + (k & 1))] = __float2half(x[i]);
}

// ---------------- fp16 mma.sync m16n8k16 GEMM, 3-stage cp.async (LM head) ----------------
// C[m,n] = sum_k A[m,k]*W[n,k]. 128x128 block, 8 warps (2x4), warp tile 64x32,
// BK=32 (2 k16-steps). Fragments come as ONE uint4 per row per chunk (pair-perm).
__global__ void __launch_bounds__(256, 2) lm_f16(const __half* __restrict__ A,
                                                 const __half* __restrict__ W,
                                                 float* __restrict__ C,
                                                 int M, int N, int K) {
    extern __shared__ __half sh16[];              // 3 stages x (A 4096 | W 4096) halves
    const uint32_t sb = smem_u32(sh16);

    const int bm = blockIdx.y * 128, bn = blockIdx.x * 128;
    const int tid = threadIdx.x;
    const int warp = tid >> 5, lane = tid & 31;
    const int wm = warp >> 2, wn = warp & 3;
    const int gid = lane >> 2, qid = lane & 3;
    const int nchunks = K >> 5;                   // 8

    auto issue = [&](int ch, int s) {
        const uint32_t abase = sb + (uint32_t)(s * 8192) * 2u;
        const uint32_t wbase = abase + 4096u * 2u;
        #pragma unroll
        for (int t = 0; t < 2; t++) {
            int c2 = tid + t * 256;               // 0..511
            int row = c2 >> 2, seg = (c2 & 3) << 3;  // seg in halves (8 halves=16B)
            uint32_t dst = (uint32_t)(row * 32 + seg) * 2u;
            CP_ASYNC16(abase + dst, A + (size_t)(bm + row) * K + ch * 32 + seg);
            CP_ASYNC16(wbase + dst, W + (size_t)(bn + row) * K + ch * 32 + seg);
        }
    };

    float cacc[4][4][4];
    #pragma unroll
    for (int i = 0; i < 4; i++)
        #pragma unroll
        for (int j = 0; j < 4; j++)
            #pragma unroll
            for (int f = 0; f < 4; f++) cacc[i][j][f] = 0.0f;

    issue(0, 0); CP_COMMIT();
    issue(1, 1); CP_COMMIT();

    for (int ch = 0; ch < nchunks; ch++) {
        const int s = ch % 3;
        CP_WAIT1();
        __syncthreads();
        if (ch + 2 < nchunks) {
            issue(ch + 2, (ch + 2) % 3);
            CP_COMMIT();
        }
        const __half* Ab = sh16 + s * 8192;
        const __half* Wb = Ab + 4096;

        uint4 bb[4];
        #pragma unroll
        for (int nt = 0; nt < 4; nt++) {
            int rn = wn * 32 + nt * 8 + gid;
            bb[nt] = *(const uint4*)&Wb[rn * 32 + qid * 8];
        }
        #pragma unroll
        for (int mt = 0; mt < 4; mt++) {
            int r0 = wm * 64 + mt * 16 + gid;
            uint4 lo = *(const uint4*)&Ab[r0 * 32 + qid * 8];
            uint4 hi = *(const uint4*)&Ab[(r0 + 8) * 32 + qid * 8];
            #pragma unroll
            for (int nt = 0; nt < 4; nt++) {
                asm volatile(
                    "mma.sync.aligned.m16n8k16.row.col.f32.f16.f16.f32 "
                    "{%0,%1,%2,%3}, {%4,%5,%6,%7}, {%8,%9}, {%0,%1,%2,%3};\n"
                    : "+f"(cacc[mt][nt][0]), "+f"(cacc[mt][nt][1]),
                      "+f"(cacc[mt][nt][2]), "+f"(cacc[mt][nt][3])
                    : "r"(lo.x), "r"(hi.x), "r"(lo.y), "r"(hi.y),
                      "r"(bb[nt].x), "r"(bb[nt].y));
                asm volatile(
                    "mma.sync.aligned.m16n8k16.row.col.f32.f16.f16.f32 "
                    "{%0,%1,%2,%3}, {%4,%5,%6,%7}, {%8,%9}, {%0,%1,%2,%3};\n"
                    : "+f"(cacc[mt][nt][0]), "+f"(cacc[mt][nt][1]),
                      "+f"(cacc[mt][nt][2]), "+f"(cacc[mt][nt][3])
                    : "r"(lo.z), "r"(hi.z), "r"(lo.w), "r"(hi.w),
                      "r"(bb[nt].z), "r"(bb[nt].w));
            }
        }
    }

    #pragma unroll
    for (int mt = 0; mt < 4; mt++) {
        int row = bm + wm * 64 + mt * 16 + gid;
        #pragma unroll
        for (int nt = 0; nt < 4; nt++) {
            int col = bn + wn * 32 + nt * 8 + qid * 2;
            *(float2*)(C + (size_t)row * N + col) =
                make_float2(cacc[mt][nt][0], cacc[mt][nt][1]);
            *(float2*)(C + (size_t)(row + 8) * N + col) =
                make_float2(cacc[mt][nt][2], cacc[mt][nt][3]);
        }
    }
}

// ---------------- classifier heads on cls token (b, 0) ----------------
__global__ void heads_k(const float* __restrict__ xn,
                        const float* __restrict__ rw, const float* __restrict__ rb,
                        const float* __restrict__ mw, const float* __restrict__ mb,
                        float* __restrict__ out) {
    int b = blockIdx.x;
    int t = threadIdx.x;
    float xv = xn[((size_t)b * L_) * D_ + t];
    float pr = xv * rw[t];
    float pm = xv * mw[t];
    __shared__ float sr[8], sm_[8];
    #pragma unroll
    for (int o = 16; o; o >>= 1) {
        pr += __shfl_xor_sync(0xFFFFFFFFu, pr, o);
        pm += __shfl_xor_sync(0xFFFFFFFFu, pm, o);
    }
    if ((t & 31) == 0) { sr[t >> 5] = pr; sm_[t >> 5] = pm; }
    __syncthreads();
    if (t == 0) {
        float a = 0.0f, c = 0.0f;
        #pragma unroll
        for (int i = 0; i < 8; i++) { a += sr[i]; c += sm_[i]; }
        out[b]      = a + rb[0];
        out[B_ + b] = c + mb[0];
    }
}

// ---------------- driver ----------------
extern "C" void kernel_launch(void* const* d_in, const int* in_sizes, int n_in,
                              void* d_out, int out_size) {
    const int*   token_ids    = (const int*)  d_in[0];
    const int*   token_types  = (const int*)  d_in[1];
    const int*   amask        = (const int*)  d_in[2];
    const float* tok_emb      = (const float*)d_in[3];
    const float* type_emb     = (const float*)d_in[4];
    const float* norm1_w      = (const float*)d_in[5];
    const float* wq           = (const float*)d_in[6];
    const float* wk           = (const float*)d_in[7];
    const float* wv           = (const float*)d_in[8];
    const float* wo           = (const float*)d_in[9];
    const float* norm2_w      = (const float*)d_in[10];
    const float* ff_w1        = (const float*)d_in[11];
    const float* ff_w2        = (const float*)d_in[12];
    const float* final_norm_w = (const float*)d_in[13];
    const float* lm_w         = (const float*)d_in[14];
    const float* read_w       = (const float*)d_in[15];
    const float* read_b       = (const float*)d_in[16];
    const float* mort_w       = (const float*)d_in[17];
    const float* mort_b       = (const float*)d_in[18];
    float* out = (float*)d_out;

    float *x, *xn, *q, *k, *v, *at, *ff;
    __half *a16, *w16;
    cudaGetSymbolAddress((void**)&x,   g_x);
    cudaGetSymbolAddress((void**)&xn,  g_xn);
    cudaGetSymbolAddress((void**)&q,   g_q);
    cudaGetSymbolAddress((void**)&k,   g_k);
    cudaGetSymbolAddress((void**)&v,   g_v);
    cudaGetSymbolAddress((void**)&at,  g_at);
    cudaGetSymbolAddress((void**)&ff,  g_ff);
    cudaGetSymbolAddress((void**)&a16, g_a16);
    cudaGetSymbolAddress((void**)&w16, g_w16);

    cudaFuncSetAttribute(lm_f16, cudaFuncAttributeMaxDynamicSharedMemorySize, 49152);

    embed_k<<<MTOK * D_ / 256, 256>>>(token_ids, token_types, tok_emb, type_emb, x);

    dim3 gqkv(D_ / 64, MTOK / 128);
    dim3 gqkv3(3 * D_ / 64, MTOK / 128);
    dim3 gff1(FF_ / 64, MTOK / 128);
    for (int li = 0; li < NL_; li++) {
        rms_k<<<MTOK, 256>>>(x, norm1_w + li * D_, xn);
        gemm_qkv<<<gqkv3, 256>>>(xn, wq + (size_t)li * D_ * D_, wk + (size_t)li * D_ * D_,
                                 wv + (size_t)li * D_ * D_, q, k, v, D_);
        rope_k<<<MTOK * H_ * 32 / 256, 256>>>(q, k);
        attn_k<<<dim3(L_ / 128, H_, B_), 128>>>(q, k, v, amask, at);
        gemm_f32<1><<<gqkv, 256>>>(at, wo + (size_t)li * D_ * D_, x, x, MTOK, D_, D_);
        rms_k<<<MTOK, 256>>>(x, norm2_w + li * D_, xn);
        gemm_f32<2><<<gff1, 256>>>(xn, ff_w1 + (size_t)li * FF_ * D_, nullptr, ff, MTOK, FF_, D_);
        gemm_f32<1><<<gqkv, 256>>>(ff, ff_w2 + (size_t)li * D_ * FF_, x, x, MTOK, D_, FF_);
    }
    rms_k<<<MTOK, 256>>>(x, final_norm_w, xn);
    cvt_f16_perm<<<MTOK * D_ / 256, 256>>>(xn, a16);
    cvt_f16_perm<<<V_ * D_ / 256, 256>>>(lm_w, w16);
    lm_f16<<<dim3(V_ / 128, MTOK / 128), 256, 49152>>>(a16, w16, out, MTOK, V_, D_);
    heads_k<<<B_, 256>>>(xn, read_w, read_b, mort_w, mort_b, out + (size_t)MTOK * V_);
}